// round 1
// baseline (speedup 1.0000x reference)
#include <cuda_runtime.h>
#include <cuda_bf16.h>
#include <math_constants.h>
#include <cstdint>

// Problem constants
#define Bb 4
#define Nn 2048
#define Cc 768
#define Hh 12
#define Dd 64
#define Mm (Bb * Nn)        // 8192
#define QKVC (3 * Cc)       // 2304
#define BH (Bb * Hh)        // 48

// ---------------- scratch (device globals; no allocation allowed) ----------
__device__ float g_qkv[(size_t)Mm * QKVC];       // [M, 2304]
__device__ float g_q[(size_t)BH * Dd * Nn];      // [BH, D, N]  (d-major!)
__device__ float g_k[(size_t)BH * Dd * Nn];      // [BH, D, N]
__device__ float g_v[(size_t)BH * Nn * Dd];      // [BH, N, D]
__device__ float g_o[(size_t)BH * Nn * Dd];      // [BH, N, D]

// ---------------------------------------------------------------------------
// SGEMM: C[M,N] = A[M,K] @ B[K,N] (+bias). 128x128x8 tile, 256 thr, 8x8 micro.
// REMAP: A is read from [B,H,N,D] layout (attention output) as logical [M, C].
// ---------------------------------------------------------------------------
template<bool REMAP, bool BIAS>
__global__ __launch_bounds__(256) void sgemm_k(
    const float* __restrict__ A, const float* __restrict__ Bm,
    const float* __restrict__ bias, float* __restrict__ C,
    int M, int N, int K)
{
    __shared__ float As[8][128];   // transposed: As[k][m]
    __shared__ float Bs[8][128];   // Bs[k][n]

    const int tid = threadIdx.x;
    const int tx  = tid & 15;      // n micro-tile
    const int ty  = tid >> 4;      // m micro-tile
    const int m0  = blockIdx.y * 128;
    const int n0  = blockIdx.x * 128;

    const int arow = tid >> 1;          // 0..127
    const int acol = (tid & 1) * 4;     // 0 or 4
    const int brL  = tid >> 5;          // 0..7
    const int bcL  = (tid & 31) * 4;    // 0..124

    float acc[8][8];
    #pragma unroll
    for (int i = 0; i < 8; i++)
        #pragma unroll
        for (int j = 0; j < 8; j++) acc[i][j] = 0.f;

    for (int k0 = 0; k0 < K; k0 += 8) {
        float4 av;
        if (REMAP) {
            int gm = m0 + arow, gk = k0 + acol;
            int b = gm >> 11, n = gm & 2047, h = gk >> 6, d = gk & 63;
            av = *(const float4*)(A + ((((size_t)(b * Hh + h) << 11) + n) << 6) + d);
        } else {
            av = *(const float4*)(A + (size_t)(m0 + arow) * K + k0 + acol);
        }
        As[acol + 0][arow] = av.x;
        As[acol + 1][arow] = av.y;
        As[acol + 2][arow] = av.z;
        As[acol + 3][arow] = av.w;
        *(float4*)&Bs[brL][bcL] =
            *(const float4*)(Bm + (size_t)(k0 + brL) * N + n0 + bcL);
        __syncthreads();

        #pragma unroll
        for (int kk = 0; kk < 8; kk++) {
            float aF[8], bF[8];
            *(float4*)(aF)     = *(float4*)&As[kk][ty * 8];
            *(float4*)(aF + 4) = *(float4*)&As[kk][ty * 8 + 4];
            *(float4*)(bF)     = *(float4*)&Bs[kk][tx * 8];
            *(float4*)(bF + 4) = *(float4*)&Bs[kk][tx * 8 + 4];
            #pragma unroll
            for (int i = 0; i < 8; i++)
                #pragma unroll
                for (int j = 0; j < 8; j++)
                    acc[i][j] += aF[i] * bF[j];
        }
        __syncthreads();
    }

    #pragma unroll
    for (int i = 0; i < 8; i++) {
        int gm = m0 + ty * 8 + i;
        #pragma unroll
        for (int j4 = 0; j4 < 8; j4 += 4) {
            int gn = n0 + tx * 8 + j4;
            float4 v;
            v.x = acc[i][j4 + 0];
            v.y = acc[i][j4 + 1];
            v.z = acc[i][j4 + 2];
            v.w = acc[i][j4 + 3];
            if (BIAS) {
                v.x += bias[gn + 0];
                v.y += bias[gn + 1];
                v.z += bias[gn + 2];
                v.w += bias[gn + 3];
            }
            *(float4*)(C + (size_t)gm * N + gn) = v;
        }
    }
}

// ---------------------------------------------------------------------------
// LayerNorm + split. One warp per (token, head). q,k -> [BH, D, N] (d-major),
// v -> [BH, N, D]. q gets *D^-0.5.
// ---------------------------------------------------------------------------
__global__ __launch_bounds__(384) void ln_split_k(
    const float* __restrict__ qkv,
    const float* __restrict__ qg, const float* __restrict__ qb,
    const float* __restrict__ kg, const float* __restrict__ kb,
    float* __restrict__ Qo, float* __restrict__ Ko, float* __restrict__ Vo)
{
    const int token = blockIdx.x;            // b*N + n
    const int b = token >> 11, n = token & 2047;
    const int h = threadIdx.x >> 5, lane = threadIdx.x & 31;
    const float* row = qkv + (size_t)token * QKVC + h * 64;
    const size_t dnBase = ((size_t)(b * Hh + h) * 64) * Nn + n;   // (bh*64 + d)*N + n

    // ---- q ----
    {
        float x0 = row[lane], x1 = row[lane + 32];
        float s = x0 + x1, sq = x0 * x0 + x1 * x1;
        #pragma unroll
        for (int off = 16; off; off >>= 1) {
            s  += __shfl_xor_sync(0xffffffffu, s,  off);
            sq += __shfl_xor_sync(0xffffffffu, sq, off);
        }
        float mean = s * (1.f / 64.f);
        float var  = sq * (1.f / 64.f) - mean * mean;
        float rstd = rsqrtf(var + 1e-5f);
        Qo[dnBase + (size_t)lane * Nn] =
            ((x0 - mean) * rstd * qg[lane] + qb[lane]) * 0.125f;
        Qo[dnBase + (size_t)(lane + 32) * Nn] =
            ((x1 - mean) * rstd * qg[lane + 32] + qb[lane + 32]) * 0.125f;
    }
    // ---- k ----
    {
        float x0 = row[768 + lane], x1 = row[768 + lane + 32];
        float s = x0 + x1, sq = x0 * x0 + x1 * x1;
        #pragma unroll
        for (int off = 16; off; off >>= 1) {
            s  += __shfl_xor_sync(0xffffffffu, s,  off);
            sq += __shfl_xor_sync(0xffffffffu, sq, off);
        }
        float mean = s * (1.f / 64.f);
        float var  = sq * (1.f / 64.f) - mean * mean;
        float rstd = rsqrtf(var + 1e-5f);
        Ko[dnBase + (size_t)lane * Nn] =
            (x0 - mean) * rstd * kg[lane] + kb[lane];
        Ko[dnBase + (size_t)(lane + 32) * Nn] =
            (x1 - mean) * rstd * kg[lane + 32] + kb[lane + 32];
    }
    // ---- v (plain copy, [BH, N, D]) ----
    {
        const size_t vBase = ((size_t)(b * Hh + h) * Nn + n) * 64;
        Vo[vBase + lane]      = row[1536 + lane];
        Vo[vBase + lane + 32] = row[1536 + lane + 32];
    }
}

// ---------------------------------------------------------------------------
// Flash attention, fp32. 64-row Q tiles, 64-key tiles, online softmax.
// Q,K in [BH, D, N]; V,O in [BH, N, D]. Block: 256 thr (16x16), 4x4 micro.
// Shared: Qs[d][r], Ks[d][c], Vs[k][d], Ps[k][r] (xor-swizzled). 64 KB dynamic.
// ---------------------------------------------------------------------------
__global__ __launch_bounds__(256) void attn_k(
    const float* __restrict__ Qg, const float* __restrict__ Kg,
    const float* __restrict__ Vg, float* __restrict__ Og)
{
    extern __shared__ float sm[];
    float* Qs = sm;               // [64][64]
    float* Ks = sm + 4096;        // [64][64]
    float* Vs = sm + 8192;        // [64][64]
    float* Ps = sm + 12288;       // [64][64] swizzled

    const int tid = threadIdx.x;
    const int tx = tid & 15, ty = tid >> 4;
    const int bh = blockIdx.y;
    const int q0 = blockIdx.x * 64;
    const size_t dnBase = (size_t)bh * 64 * Nn;

    // Q tile load: Qs[d][r]
    #pragma unroll
    for (int t = tid; t < 1024; t += 256) {
        int d = t >> 4, r4 = (t & 15) << 2;
        *(float4*)&Qs[d * 64 + r4] =
            *(const float4*)&Qg[dnBase + (size_t)d * Nn + q0 + r4];
    }

    float m[4], l[4], o[4][4];
    #pragma unroll
    for (int i = 0; i < 4; i++) {
        m[i] = -CUDART_INF_F; l[i] = 0.f;
        #pragma unroll
        for (int j = 0; j < 4; j++) o[i][j] = 0.f;
    }
    __syncthreads();

    for (int kt = 0; kt < Nn / 64; kt++) {
        const int k0 = kt * 64;
        #pragma unroll
        for (int t = tid; t < 1024; t += 256) {
            int d = t >> 4, c4 = (t & 15) << 2;
            *(float4*)&Ks[d * 64 + c4] =
                *(const float4*)&Kg[dnBase + (size_t)d * Nn + k0 + c4];
        }
        #pragma unroll
        for (int t = tid; t < 1024; t += 256) {
            int k = t >> 4, d4 = (t & 15) << 2;
            *(float4*)&Vs[k * 64 + d4] =
                *(const float4*)&Vg[((size_t)bh * Nn + k0 + k) * 64 + d4];
        }
        __syncthreads();

        // S = Q K^T (64x64 tile; this thread: rows ty*4.., cols tx*4..)
        float s[4][4];
        #pragma unroll
        for (int i = 0; i < 4; i++)
            #pragma unroll
            for (int j = 0; j < 4; j++) s[i][j] = 0.f;

        #pragma unroll 8
        for (int d = 0; d < 64; d++) {
            float4 aF = *(float4*)&Qs[d * 64 + ty * 4];
            float4 bF = *(float4*)&Ks[d * 64 + tx * 4];
            s[0][0] += aF.x * bF.x; s[0][1] += aF.x * bF.y;
            s[0][2] += aF.x * bF.z; s[0][3] += aF.x * bF.w;
            s[1][0] += aF.y * bF.x; s[1][1] += aF.y * bF.y;
            s[1][2] += aF.y * bF.z; s[1][3] += aF.y * bF.w;
            s[2][0] += aF.z * bF.x; s[2][1] += aF.z * bF.y;
            s[2][2] += aF.z * bF.z; s[2][3] += aF.z * bF.w;
            s[3][0] += aF.w * bF.x; s[3][1] += aF.w * bF.y;
            s[3][2] += aF.w * bF.z; s[3][3] += aF.w * bF.w;
        }

        // online softmax (row reductions over the 16 lanes sharing ty)
        #pragma unroll
        for (int i = 0; i < 4; i++) {
            float mt = fmaxf(fmaxf(s[i][0], s[i][1]), fmaxf(s[i][2], s[i][3]));
            mt = fmaxf(mt, __shfl_xor_sync(0xffffffffu, mt, 1, 16));
            mt = fmaxf(mt, __shfl_xor_sync(0xffffffffu, mt, 2, 16));
            mt = fmaxf(mt, __shfl_xor_sync(0xffffffffu, mt, 4, 16));
            mt = fmaxf(mt, __shfl_xor_sync(0xffffffffu, mt, 8, 16));
            float mn = fmaxf(m[i], mt);
            float corr = __expf(m[i] - mn);
            float ps = 0.f;
            #pragma unroll
            for (int j = 0; j < 4; j++) {
                float p = __expf(s[i][j] - mn);
                ps += p;
                // store P[r=ty*4+i][k=tx*4+j] swizzled: Ps[k][ (ty^tx)*4 + i ]
                Ps[(tx * 4 + j) * 64 + ((ty ^ tx) << 2) + i] = p;
            }
            ps += __shfl_xor_sync(0xffffffffu, ps, 1, 16);
            ps += __shfl_xor_sync(0xffffffffu, ps, 2, 16);
            ps += __shfl_xor_sync(0xffffffffu, ps, 4, 16);
            ps += __shfl_xor_sync(0xffffffffu, ps, 8, 16);
            l[i] = l[i] * corr + ps;
            m[i] = mn;
            o[i][0] *= corr; o[i][1] *= corr; o[i][2] *= corr; o[i][3] *= corr;
        }
        __syncthreads();

        // O += P V (this thread: rows ty*4.., d-cols tx*4..)
        #pragma unroll 8
        for (int k = 0; k < 64; k++) {
            float4 pF = *(float4*)&Ps[k * 64 + ((ty ^ (k >> 2)) << 2)];
            float4 vF = *(float4*)&Vs[k * 64 + tx * 4];
            o[0][0] += pF.x * vF.x; o[0][1] += pF.x * vF.y;
            o[0][2] += pF.x * vF.z; o[0][3] += pF.x * vF.w;
            o[1][0] += pF.y * vF.x; o[1][1] += pF.y * vF.y;
            o[1][2] += pF.y * vF.z; o[1][3] += pF.y * vF.w;
            o[2][0] += pF.z * vF.x; o[2][1] += pF.z * vF.y;
            o[2][2] += pF.z * vF.z; o[2][3] += pF.z * vF.w;
            o[3][0] += pF.w * vF.x; o[3][1] += pF.w * vF.y;
            o[3][2] += pF.w * vF.z; o[3][3] += pF.w * vF.w;
        }
        __syncthreads();
    }

    #pragma unroll
    for (int i = 0; i < 4; i++) {
        float inv = 1.f / l[i];
        float4 v;
        v.x = o[i][0] * inv; v.y = o[i][1] * inv;
        v.z = o[i][2] * inv; v.w = o[i][3] * inv;
        *(float4*)&Og[((size_t)bh * Nn + q0 + ty * 4 + i) * 64 + tx * 4] = v;
    }
}

// ---------------------------------------------------------------------------
extern "C" void kernel_launch(void* const* d_in, const int* in_sizes, int n_in,
                              void* d_out, int out_size)
{
    const float* x       = (const float*)d_in[0];
    const float* w_qkv   = (const float*)d_in[1];
    const float* q_gamma = (const float*)d_in[2];
    const float* q_beta  = (const float*)d_in[3];
    const float* k_gamma = (const float*)d_in[4];
    const float* k_beta  = (const float*)d_in[5];
    const float* w_proj  = (const float*)d_in[6];
    const float* b_proj  = (const float*)d_in[7];
    float* out = (float*)d_out;

    float *qkv, *q, *k, *v, *o;
    cudaGetSymbolAddress((void**)&qkv, g_qkv);
    cudaGetSymbolAddress((void**)&q,   g_q);
    cudaGetSymbolAddress((void**)&k,   g_k);
    cudaGetSymbolAddress((void**)&v,   g_v);
    cudaGetSymbolAddress((void**)&o,   g_o);

    // 1) qkv = x @ w_qkv
    sgemm_k<false, false><<<dim3(QKVC / 128, Mm / 128), 256>>>(
        x, w_qkv, nullptr, qkv, Mm, QKVC, Cc);

    // 2) LayerNorm q,k (+scale q) and split into d-major q,k + v
    ln_split_k<<<Mm, 384>>>(qkv, q_gamma, q_beta, k_gamma, k_beta, q, k, v);

    // 3) flash attention
    cudaFuncSetAttribute(attn_k, cudaFuncAttributeMaxDynamicSharedMemorySize, 65536);
    attn_k<<<dim3(Nn / 64, BH), 256, 65536>>>(q, k, v, o);

    // 4) out = attn_out @ w_proj + b
    sgemm_k<true, true><<<dim3(Cc / 128, Mm / 128), 256>>>(
        o, w_proj, b_proj, out, Mm, Cc, Cc);
}

// round 4
// speedup vs baseline: 2.8526x; 2.8526x over previous
#include <cuda_runtime.h>
#include <cuda_bf16.h>
#include <math_constants.h>
#include <cstdint>

// Problem constants
#define Bb 4
#define Nn 2048
#define Cc 768
#define Hh 12
#define Dd 64
#define Mm (Bb * Nn)        // 8192
#define QKVC (3 * Cc)       // 2304
#define BH (Bb * Hh)        // 48

// ---------------- scratch (device globals; no allocation allowed) ----------
__device__ float g_qkv[(size_t)Mm * QKVC];       // [M, 2304]
__device__ float g_q[(size_t)BH * Nn * Dd];      // [BH, N, D] row-major
__device__ float g_k[(size_t)BH * Nn * Dd];      // [BH, N, D] row-major
__device__ float g_v[(size_t)BH * Dd * Nn];      // [BH, D, N] d-major (= V^T)
__device__ float g_o[(size_t)BH * Nn * Dd];      // [BH, N, D]

// ===========================================================================
// helpers
// ===========================================================================
__device__ __forceinline__ float to_tf32(float x) {
    uint32_t u;
    asm("cvt.rna.tf32.f32 %0, %1;" : "=r"(u) : "f"(x));
    return __uint_as_float(u);
}
// D += A*B, m16n8k8 tf32 (A row-major frag, B "col" frag = element (k,n))
__device__ __forceinline__ void mma8(float* d, const uint32_t* a, const uint32_t* b) {
    asm volatile(
        "mma.sync.aligned.m16n8k8.row.col.f32.tf32.tf32.f32 "
        "{%0,%1,%2,%3}, {%4,%5,%6,%7}, {%8,%9}, {%0,%1,%2,%3};\n"
        : "+f"(d[0]), "+f"(d[1]), "+f"(d[2]), "+f"(d[3])
        : "r"(a[0]), "r"(a[1]), "r"(a[2]), "r"(a[3]),
          "r"(b[0]), "r"(b[1]));
}
__device__ __forceinline__ uint32_t fu(float x) { return __float_as_uint(x); }

// ===========================================================================
// mma.sync tf32 GEMM: C[M,N] = A[M,K] @ B[K,N] (+bias).
// 128x128 CTA tile, 256 thr (8 warps, 2x4), warp tile 64x32, k-chunk 32.
// Smem: As[128][36] (A-frag conflict-free), Bs[32][136] (B-frag conflict-free).
// Register-staged prefetch: LDG for chunk it+1 issued before compute(it).
// REMAP: A read from [BH, N, D] attention-output layout as logical [M, C].
// ===========================================================================
template<bool REMAP, bool BIAS>
__global__ __launch_bounds__(256) void gemm_mma(
    const float* __restrict__ A, const float* __restrict__ Bm,
    const float* __restrict__ bias, float* __restrict__ C,
    int Nc, int K)
{
    extern __shared__ float sg[];
    float* As = sg;            // 128*36 = 4608 floats
    float* Bs = sg + 4608;     // 32*136 = 4352 floats  (total 35840 B)

    const int tid  = threadIdx.x;
    const int lane = tid & 31, wid = tid >> 5;
    const int g = lane >> 2, tg = lane & 3;
    const int wm = (wid & 1) * 64, wn = (wid >> 1) * 32;
    const int m0 = blockIdx.y * 128, n0 = blockIdx.x * 128;

    float acc[4][4][4];
    #pragma unroll
    for (int i = 0; i < 4; i++)
        #pragma unroll
        for (int j = 0; j < 4; j++)
            #pragma unroll
            for (int r = 0; r < 4; r++) acc[i][j][r] = 0.f;

    float4 ra[4], rb[4];

    // ---- loaders into registers ----
    auto loadA = [&](int k0) {
        #pragma unroll
        for (int i = 0; i < 4; i++) {
            int idx = tid + i * 256;
            int row = idx >> 3, kk = (idx & 7) * 4;
            if (REMAP) {
                int gk = k0 + kk;
                int h = gk >> 6, d0 = gk & 63;
                int gm = m0 + row, b = gm >> 11, n = gm & 2047;
                ra[i] = *(const float4*)(A +
                    (((size_t)(b * Hh + h) * Nn + n) << 6) + d0);
            } else {
                ra[i] = *(const float4*)(A + (size_t)(m0 + row) * K + k0 + kk);
            }
        }
    };
    auto loadB = [&](int k0) {
        #pragma unroll
        for (int i = 0; i < 4; i++) {
            int idx = tid + i * 256;
            int kr = idx >> 5, n4 = (idx & 31) * 4;
            rb[i] = *(const float4*)(Bm + (size_t)(k0 + kr) * Nc + n0 + n4);
        }
    };

    loadA(0); loadB(0);
    const int ITERS = K / 32;

    for (int it = 0; it < ITERS; ++it) {
        // commit staged regs -> smem (tf32-round here)
        #pragma unroll
        for (int i = 0; i < 4; i++) {
            int idx = tid + i * 256;
            int row = idx >> 3, kk = (idx & 7) * 4;
            float4 v = ra[i], w;
            w.x = to_tf32(v.x); w.y = to_tf32(v.y);
            w.z = to_tf32(v.z); w.w = to_tf32(v.w);
            *(float4*)(As + row * 36 + kk) = w;
        }
        #pragma unroll
        for (int i = 0; i < 4; i++) {
            int idx = tid + i * 256;
            int kr = idx >> 5, n4 = (idx & 31) * 4;
            float4 v = rb[i], w;
            w.x = to_tf32(v.x); w.y = to_tf32(v.y);
            w.z = to_tf32(v.z); w.w = to_tf32(v.w);
            *(float4*)(Bs + kr * 136 + n4) = w;
        }
        __syncthreads();

        if (it + 1 < ITERS) { loadA((it + 1) * 32); loadB((it + 1) * 32); }

        // ---- mma over this 32-k chunk ----
        #pragma unroll
        for (int ks = 0; ks < 4; ks++) {
            const int kk = ks * 8;
            uint32_t afr[4][4], bfr[4][2];
            #pragma unroll
            for (int mt = 0; mt < 4; mt++) {
                const float* ab = As + (wm + mt * 16 + g) * 36 + kk + tg;
                afr[mt][0] = fu(ab[0]);
                afr[mt][1] = fu(ab[8 * 36]);
                afr[mt][2] = fu(ab[4]);
                afr[mt][3] = fu(ab[8 * 36 + 4]);
            }
            #pragma unroll
            for (int nt = 0; nt < 4; nt++) {
                const float* bb = Bs + (kk + tg) * 136 + wn + nt * 8 + g;
                bfr[nt][0] = fu(bb[0]);
                bfr[nt][1] = fu(bb[4 * 136]);
            }
            #pragma unroll
            for (int mt = 0; mt < 4; mt++)
                #pragma unroll
                for (int nt = 0; nt < 4; nt++)
                    mma8(acc[mt][nt], afr[mt], bfr[nt]);
        }
        __syncthreads();
    }

    // ---- epilogue ----
    #pragma unroll
    for (int mt = 0; mt < 4; mt++) {
        const int r0 = m0 + wm + mt * 16 + g;
        #pragma unroll
        for (int nt = 0; nt < 4; nt++) {
            const int col = n0 + wn + nt * 8 + 2 * tg;
            float bx = 0.f, by = 0.f;
            if (BIAS) { bx = bias[col]; by = bias[col + 1]; }
            float2 v0 = { acc[mt][nt][0] + bx, acc[mt][nt][1] + by };
            float2 v1 = { acc[mt][nt][2] + bx, acc[mt][nt][3] + by };
            *(float2*)(C + (size_t)r0 * Nc + col) = v0;
            *(float2*)(C + (size_t)(r0 + 8) * Nc + col) = v1;
        }
    }
}

// ---------------------------------------------------------------------------
// LayerNorm + split. One warp per (token, head).
// q,k -> [BH, N, D] row-major (coalesced), v -> [BH, D, N] (= V^T).
// q gets *D^-0.5. All outputs tf32-rounded.
// ---------------------------------------------------------------------------
__global__ __launch_bounds__(384) void ln_split_k(
    const float* __restrict__ qkv,
    const float* __restrict__ qg, const float* __restrict__ qb,
    const float* __restrict__ kg, const float* __restrict__ kb,
    float* __restrict__ Qo, float* __restrict__ Ko, float* __restrict__ Vo)
{
    const int token = blockIdx.x;            // b*N + n
    const int b = token >> 11, n = token & 2047;
    const int h = threadIdx.x >> 5, lane = threadIdx.x & 31;
    const float* row = qkv + (size_t)token * QKVC + h * 64;
    const size_t qkBase = ((size_t)(b * Hh + h) * Nn + n) * 64;

    // ---- q ----
    {
        float x0 = row[lane], x1 = row[lane + 32];
        float s = x0 + x1, sq = x0 * x0 + x1 * x1;
        #pragma unroll
        for (int off = 16; off; off >>= 1) {
            s  += __shfl_xor_sync(0xffffffffu, s,  off);
            sq += __shfl_xor_sync(0xffffffffu, sq, off);
        }
        float mean = s * (1.f / 64.f);
        float var  = sq * (1.f / 64.f) - mean * mean;
        float rstd = rsqrtf(var + 1e-5f);
        Qo[qkBase + lane] =
            to_tf32(((x0 - mean) * rstd * qg[lane] + qb[lane]) * 0.125f);
        Qo[qkBase + lane + 32] =
            to_tf32(((x1 - mean) * rstd * qg[lane + 32] + qb[lane + 32]) * 0.125f);
    }
    // ---- k ----
    {
        float x0 = row[768 + lane], x1 = row[768 + lane + 32];
        float s = x0 + x1, sq = x0 * x0 + x1 * x1;
        #pragma unroll
        for (int off = 16; off; off >>= 1) {
            s  += __shfl_xor_sync(0xffffffffu, s,  off);
            sq += __shfl_xor_sync(0xffffffffu, sq, off);
        }
        float mean = s * (1.f / 64.f);
        float var  = sq * (1.f / 64.f) - mean * mean;
        float rstd = rsqrtf(var + 1e-5f);
        Ko[qkBase + lane] =
            to_tf32((x0 - mean) * rstd * kg[lane] + kb[lane]);
        Ko[qkBase + lane + 32] =
            to_tf32((x1 - mean) * rstd * kg[lane + 32] + kb[lane + 32]);
    }
    // ---- v -> transposed [BH, D, N] ----
    {
        const size_t vBase = ((size_t)(b * Hh + h) * Dd) * Nn + n;
        Vo[vBase + (size_t)lane * Nn]        = to_tf32(row[1536 + lane]);
        Vo[vBase + (size_t)(lane + 32) * Nn] = to_tf32(row[1536 + lane + 32]);
    }
}

// ---------------------------------------------------------------------------
// Flash attention via mma.sync tf32. 64-q tiles, 64-kv tiles, online softmax.
// Block 128 thr = 4 warps; warp w owns q-rows [w*16, w*16+16).
// Q,K in [BH,N,D]; V in [BH,D,N] (V^T); O out [BH,N,D].
// Smem: Qs/Ks/Vs/Ps each [64][68] floats = 69632 B total.
// ---------------------------------------------------------------------------
__global__ __launch_bounds__(128) void attn_mma(
    const float* __restrict__ Qg, const float* __restrict__ Kg,
    const float* __restrict__ Vg, float* __restrict__ Og)
{
    extern __shared__ float sg[];
    float* Qs = sg;            // [64][68]
    float* Ks = sg + 4352;
    float* Vs = sg + 8704;
    float* Ps = sg + 13056;

    const int tid = threadIdx.x, lane = tid & 31, w = tid >> 5;
    const int g = lane >> 2, tg = lane & 3;
    const int bh = blockIdx.y, q0 = blockIdx.x * 64;

    const float* Qp = Qg + ((size_t)bh * Nn + q0) * 64;
    const float* Kp = Kg + (size_t)bh * Nn * 64;
    const float* Vp = Vg + (size_t)bh * 64 * Nn;

    // load Q tile (already tf32-rounded by ln_split)
    #pragma unroll
    for (int i = 0; i < 8; i++) {
        int idx = tid + i * 128;
        int row = idx >> 4, c4 = (idx & 15) * 4;
        *(float4*)(Qs + row * 68 + c4) = *(const float4*)(Qp + row * 64 + c4);
    }

    // stage K,V tile 0
    float4 kst[8], vst[8];
    #pragma unroll
    for (int i = 0; i < 8; i++) {
        int idx = tid + i * 128;
        int row = idx >> 4, c4 = (idx & 15) * 4;
        kst[i] = *(const float4*)(Kp + (size_t)row * 64 + c4);
        vst[i] = *(const float4*)(Vp + (size_t)row * Nn + c4);
    }

    float mrow0 = -CUDART_INF_F, mrow1 = -CUDART_INF_F;
    float lrow0 = 0.f, lrow1 = 0.f;
    float o[8][4];
    #pragma unroll
    for (int i = 0; i < 8; i++)
        #pragma unroll
        for (int j = 0; j < 4; j++) o[i][j] = 0.f;

    __syncthreads();   // Qs visible before first S-mma (paired with loop syncs)

    for (int it = 0; it < 32; ++it) {
        // commit staged K,V
        #pragma unroll
        for (int i = 0; i < 8; i++) {
            int idx = tid + i * 128;
            int row = idx >> 4, c4 = (idx & 15) * 4;
            *(float4*)(Ks + row * 68 + c4) = kst[i];
            *(float4*)(Vs + row * 68 + c4) = vst[i];
        }
        __syncthreads();

        if (it + 1 < 32) {
            const int k0n = (it + 1) * 64;
            #pragma unroll
            for (int i = 0; i < 8; i++) {
                int idx = tid + i * 128;
                int row = idx >> 4, c4 = (idx & 15) * 4;
                kst[i] = *(const float4*)(Kp + (size_t)(k0n + row) * 64 + c4);
                vst[i] = *(const float4*)(Vp + (size_t)row * Nn + k0n + c4);
            }
        }

        // ---- S = Q K^T (warp rows w*16..w*16+15, all 64 kv cols) ----
        float s[8][4];
        #pragma unroll
        for (int i = 0; i < 8; i++)
            #pragma unroll
            for (int j = 0; j < 4; j++) s[i][j] = 0.f;

        #pragma unroll
        for (int ks = 0; ks < 8; ks++) {
            uint32_t aq[4];
            const float* ab = Qs + (w * 16 + g) * 68 + ks * 8 + tg;
            aq[0] = fu(ab[0]);
            aq[1] = fu(ab[8 * 68]);
            aq[2] = fu(ab[4]);
            aq[3] = fu(ab[8 * 68 + 4]);
            #pragma unroll
            for (int nt = 0; nt < 8; nt++) {
                uint32_t b[2];
                const float* bb = Ks + (nt * 8 + g) * 68 + ks * 8 + tg;
                b[0] = fu(bb[0]);
                b[1] = fu(bb[4]);
                mma8(s[nt], aq, b);
            }
        }

        // ---- online softmax (thread rows: r0 = g, r1 = g+8 in warp band) ----
        float mx0 = -CUDART_INF_F, mx1 = -CUDART_INF_F;
        #pragma unroll
        for (int nt = 0; nt < 8; nt++) {
            mx0 = fmaxf(mx0, fmaxf(s[nt][0], s[nt][1]));
            mx1 = fmaxf(mx1, fmaxf(s[nt][2], s[nt][3]));
        }
        mx0 = fmaxf(mx0, __shfl_xor_sync(0xffffffffu, mx0, 1));
        mx0 = fmaxf(mx0, __shfl_xor_sync(0xffffffffu, mx0, 2));
        mx1 = fmaxf(mx1, __shfl_xor_sync(0xffffffffu, mx1, 1));
        mx1 = fmaxf(mx1, __shfl_xor_sync(0xffffffffu, mx1, 2));

        const float mn0 = fmaxf(mrow0, mx0), mn1 = fmaxf(mrow1, mx1);
        const float cr0 = __expf(mrow0 - mn0), cr1 = __expf(mrow1 - mn1);
        float ps0 = 0.f, ps1 = 0.f;
        #pragma unroll
        for (int nt = 0; nt < 8; nt++) {
            float p00 = __expf(s[nt][0] - mn0), p01 = __expf(s[nt][1] - mn0);
            float p10 = __expf(s[nt][2] - mn1), p11 = __expf(s[nt][3] - mn1);
            ps0 += p00 + p01;
            ps1 += p10 + p11;
            float2 w0 = { to_tf32(p00), to_tf32(p01) };
            float2 w1 = { to_tf32(p10), to_tf32(p11) };
            *(float2*)(Ps + (w * 16 + g) * 68 + nt * 8 + 2 * tg)     = w0;
            *(float2*)(Ps + (w * 16 + g + 8) * 68 + nt * 8 + 2 * tg) = w1;
        }
        ps0 += __shfl_xor_sync(0xffffffffu, ps0, 1);
        ps0 += __shfl_xor_sync(0xffffffffu, ps0, 2);
        ps1 += __shfl_xor_sync(0xffffffffu, ps1, 1);
        ps1 += __shfl_xor_sync(0xffffffffu, ps1, 2);
        lrow0 = lrow0 * cr0 + ps0;
        lrow1 = lrow1 * cr1 + ps1;
        mrow0 = mn0; mrow1 = mn1;
        #pragma unroll
        for (int nt = 0; nt < 8; nt++) {
            o[nt][0] *= cr0; o[nt][1] *= cr0;
            o[nt][2] *= cr1; o[nt][3] *= cr1;
        }
        __syncthreads();   // Ps visible to own warp reads? (smem write->read same
                           // warp is ordered; sync protects nothing cross-warp here
                           // but is required before Ks/Vs overwrite next iter)

        // ---- O += P V ----
        #pragma unroll
        for (int ks = 0; ks < 8; ks++) {
            uint32_t ap[4];
            const float* pb = Ps + (w * 16 + g) * 68 + ks * 8 + tg;
            ap[0] = fu(pb[0]);
            ap[1] = fu(pb[8 * 68]);
            ap[2] = fu(pb[4]);
            ap[3] = fu(pb[8 * 68 + 4]);
            #pragma unroll
            for (int nt = 0; nt < 8; nt++) {
                uint32_t b[2];
                const float* vb = Vs + (nt * 8 + g) * 68 + ks * 8 + tg;
                b[0] = fu(vb[0]);
                b[1] = fu(vb[4]);
                mma8(o[nt], ap, b);
            }
        }
        __syncthreads();   // before next iteration's Ks/Vs store
    }

    // ---- epilogue ----
    const float inv0 = 1.f / lrow0, inv1 = 1.f / lrow1;
    const int r0 = q0 + w * 16 + g;
    #pragma unroll
    for (int nt = 0; nt < 8; nt++) {
        const int col = nt * 8 + 2 * tg;
        float2 v0 = { o[nt][0] * inv0, o[nt][1] * inv0 };
        float2 v1 = { o[nt][2] * inv1, o[nt][3] * inv1 };
        *(float2*)(Og + ((size_t)bh * Nn + r0) * 64 + col) = v0;
        *(float2*)(Og + ((size_t)bh * Nn + r0 + 8) * 64 + col) = v1;
    }
}

// ---------------------------------------------------------------------------
extern "C" void kernel_launch(void* const* d_in, const int* in_sizes, int n_in,
                              void* d_out, int out_size)
{
    const float* x       = (const float*)d_in[0];
    const float* w_qkv   = (const float*)d_in[1];
    const float* q_gamma = (const float*)d_in[2];
    const float* q_beta  = (const float*)d_in[3];
    const float* k_gamma = (const float*)d_in[4];
    const float* k_beta  = (const float*)d_in[5];
    const float* w_proj  = (const float*)d_in[6];
    const float* b_proj  = (const float*)d_in[7];
    float* out = (float*)d_out;

    float *qkv, *q, *k, *v, *o;
    cudaGetSymbolAddress((void**)&qkv, g_qkv);
    cudaGetSymbolAddress((void**)&q,   g_q);
    cudaGetSymbolAddress((void**)&k,   g_k);
    cudaGetSymbolAddress((void**)&v,   g_v);
    cudaGetSymbolAddress((void**)&o,   g_o);

    const int GEMM_SMEM = 35840;
    const int ATTN_SMEM = 69632;
    cudaFuncSetAttribute(gemm_mma<false, false>,
                         cudaFuncAttributeMaxDynamicSharedMemorySize, GEMM_SMEM);
    cudaFuncSetAttribute(gemm_mma<true, true>,
                         cudaFuncAttributeMaxDynamicSharedMemorySize, GEMM_SMEM);
    cudaFuncSetAttribute(attn_mma,
                         cudaFuncAttributeMaxDynamicSharedMemorySize, ATTN_SMEM);

    // 1) qkv = x @ w_qkv   (mma.sync tf32)
    gemm_mma<false, false><<<dim3(QKVC / 128, Mm / 128), 256, GEMM_SMEM>>>(
        x, w_qkv, nullptr, qkv, QKVC, Cc);

    // 2) LayerNorm q,k (+scale q); q,k row-major, v transposed
    ln_split_k<<<Mm, 384>>>(qkv, q_gamma, q_beta, k_gamma, k_beta, q, k, v);

    // 3) flash attention (mma.sync tf32)
    attn_mma<<<dim3(Nn / 64, BH), 128, ATTN_SMEM>>>(q, k, v, o);

    // 4) out = attn_out @ w_proj + b   (mma.sync tf32)
    gemm_mma<true, true><<<dim3(Cc / 128, Mm / 128), 256, GEMM_SMEM>>>(
        o, w_proj, b_proj, out, Cc, Cc);
}

// round 6
// speedup vs baseline: 3.2147x; 1.1269x over previous
#include <cuda_runtime.h>
#include <cuda_bf16.h>
#include <math_constants.h>
#include <cstdint>

// Problem constants
#define Bb 4
#define Nn 2048
#define Cc 768
#define Hh 12
#define Dd 64
#define Mm (Bb * Nn)        // 8192
#define QKVC (3 * Cc)       // 2304
#define BH (Bb * Hh)        // 48

// ---------------- scratch (device globals; no allocation allowed) ----------
__device__ __align__(256) float g_qkv[(size_t)Mm * QKVC];  // [M, 2304]
__device__ __align__(256) float g_q[(size_t)BH * Nn * Dd]; // [BH,N,D] tf32
__device__ __align__(256) float g_k[(size_t)BH * Nn * Dd]; // [BH,N,D] tf32
__device__ __align__(256) float g_v[(size_t)BH * Nn * Dd]; // [BH,N,D] tf32
__device__ __align__(256) float g_o[(size_t)BH * Nn * Dd]; // [BH,N,D] tf32
__device__ __align__(256) float g_x[(size_t)Mm * Cc];      // tf32 x
__device__ __align__(256) float g_wq[(size_t)Cc * QKVC];   // tf32 w_qkv
__device__ __align__(256) float g_wp[(size_t)Cc * Cc];     // tf32 w_proj

// ===========================================================================
// helpers
// ===========================================================================
__device__ __forceinline__ float to_tf32(float x) {
    uint32_t u;
    asm("cvt.rna.tf32.f32 %0, %1;" : "=r"(u) : "f"(x));
    return __uint_as_float(u);
}
__device__ __forceinline__ void mma8(float* d, const uint32_t* a, const uint32_t* b) {
    asm volatile(
        "mma.sync.aligned.m16n8k8.row.col.f32.tf32.tf32.f32 "
        "{%0,%1,%2,%3}, {%4,%5,%6,%7}, {%8,%9}, {%0,%1,%2,%3};\n"
        : "+f"(d[0]), "+f"(d[1]), "+f"(d[2]), "+f"(d[3])
        : "r"(a[0]), "r"(a[1]), "r"(a[2]), "r"(a[3]),
          "r"(b[0]), "r"(b[1]));
}
__device__ __forceinline__ uint32_t fu(float x) { return __float_as_uint(x); }
__device__ __forceinline__ uint32_t smem_u32(const void* p) {
    uint32_t a;
    asm("{ .reg .u64 t; cvta.to.shared.u64 t, %1; cvt.u32.u64 %0, t; }"
        : "=r"(a) : "l"(p));
    return a;
}
__device__ __forceinline__ void cp16(uint32_t dst, const void* src) {
    asm volatile("cp.async.cg.shared.global [%0], [%1], 16;\n"
                 :: "r"(dst), "l"(src));
}
#define CP_COMMIT() asm volatile("cp.async.commit_group;\n" ::: "memory")
#define CP_WAIT(N)  asm volatile("cp.async.wait_group %0;\n" :: "n"(N) : "memory")

// ===========================================================================
// tf32 pre-round pass (elementwise, float4)
// ===========================================================================
__global__ void round4_k(const float4* __restrict__ in, float4* __restrict__ out,
                         int n4)
{
    int i = blockIdx.x * blockDim.x + threadIdx.x;
    if (i < n4) {
        float4 v = in[i];
        v.x = to_tf32(v.x); v.y = to_tf32(v.y);
        v.z = to_tf32(v.z); v.w = to_tf32(v.w);
        out[i] = v;
    }
}

// ===========================================================================
// mma.sync tf32 GEMM, cp.async 2-stage pipeline.
// C[M,N] = A[M,K] @ B[K,N] (+bias). 128x128 CTA, 256 thr, warp tile 64x32.
// A,B pre-rounded to tf32. Smem/stage: As[128][36], Bs[32][136].
// REMAP: A read from [BH, N, D] attention-output layout as logical [M, C].
// Dyn smem: 2*(4608+4352)*4 = 71680 B.
// ===========================================================================
template<bool REMAP, bool BIAS>
__global__ __launch_bounds__(256, 2) void gemm_ca(
    const float* __restrict__ A, const float* __restrict__ Bm,
    const float* __restrict__ bias, float* __restrict__ C,
    int Nc, int K)
{
    extern __shared__ float sg[];
    const uint32_t sb = smem_u32(sg);

    const int tid  = threadIdx.x;
    const int lane = tid & 31, wid = tid >> 5;
    const int g = lane >> 2, tg = lane & 3;
    const int wm = (wid & 1) * 64, wn = (wid >> 1) * 32;
    const int m0 = blockIdx.y * 128, n0 = blockIdx.x * 128;

    float acc[4][4][4];
    #pragma unroll
    for (int i = 0; i < 4; i++)
        #pragma unroll
        for (int j = 0; j < 4; j++)
            #pragma unroll
            for (int r = 0; r < 4; r++) acc[i][j][r] = 0.f;

    // stage offsets (floats)
    auto AS = [](int s) { return s * 4608; };
    auto BS = [](int s) { return 9216 + s * 4352; };

    auto issue = [&](int it, int s) {
        const int k0 = it * 32;
        #pragma unroll
        for (int i = 0; i < 4; i++) {
            int idx = tid + i * 256;
            int row = idx >> 3, kk = (idx & 7) * 4;
            const float* src;
            if (REMAP) {
                int gk = k0 + kk;
                int h = gk >> 6, d0 = gk & 63;
                int gm = m0 + row, b = gm >> 11, n = gm & 2047;
                src = A + (((size_t)(b * Hh + h) * Nn + n) << 6) + d0;
            } else {
                src = A + (size_t)(m0 + row) * K + k0 + kk;
            }
            cp16(sb + (AS(s) + row * 36 + kk) * 4, src);
        }
        #pragma unroll
        for (int i = 0; i < 4; i++) {
            int idx = tid + i * 256;
            int kr = idx >> 5, n4 = (idx & 31) * 4;
            cp16(sb + (BS(s) + kr * 136 + n4) * 4,
                 Bm + (size_t)(k0 + kr) * Nc + n0 + n4);
        }
        CP_COMMIT();
    };

    const int ITERS = K / 32;
    issue(0, 0);

    for (int it = 0; it < ITERS; ++it) {
        if (it + 1 < ITERS) { issue(it + 1, (it + 1) & 1); CP_WAIT(1); }
        else                { CP_WAIT(0); }
        __syncthreads();

        const float* As = sg + AS(it & 1);
        const float* Bs = sg + BS(it & 1);

        #pragma unroll
        for (int ks = 0; ks < 4; ks++) {
            const int kk = ks * 8;
            uint32_t afr[4][4], bfr[4][2];
            #pragma unroll
            for (int mt = 0; mt < 4; mt++) {
                const float* ab = As + (wm + mt * 16 + g) * 36 + kk + tg;
                afr[mt][0] = fu(ab[0]);
                afr[mt][1] = fu(ab[8 * 36]);
                afr[mt][2] = fu(ab[4]);
                afr[mt][3] = fu(ab[8 * 36 + 4]);
            }
            #pragma unroll
            for (int nt = 0; nt < 4; nt++) {
                const float* bb = Bs + (kk + tg) * 136 + wn + nt * 8 + g;
                bfr[nt][0] = fu(bb[0]);
                bfr[nt][1] = fu(bb[4 * 136]);
            }
            #pragma unroll
            for (int mt = 0; mt < 4; mt++)
                #pragma unroll
                for (int nt = 0; nt < 4; nt++)
                    mma8(acc[mt][nt], afr[mt], bfr[nt]);
        }
        __syncthreads();
    }

    // ---- epilogue ----
    #pragma unroll
    for (int mt = 0; mt < 4; mt++) {
        const int r0 = m0 + wm + mt * 16 + g;
        #pragma unroll
        for (int nt = 0; nt < 4; nt++) {
            const int col = n0 + wn + nt * 8 + 2 * tg;
            float bx = 0.f, by = 0.f;
            if (BIAS) { bx = bias[col]; by = bias[col + 1]; }
            float2 v0 = { acc[mt][nt][0] + bx, acc[mt][nt][1] + by };
            float2 v1 = { acc[mt][nt][2] + bx, acc[mt][nt][3] + by };
            *(float2*)(C + (size_t)r0 * Nc + col) = v0;
            *(float2*)(C + (size_t)(r0 + 8) * Nc + col) = v1;
        }
    }
}

// ---------------------------------------------------------------------------
// LayerNorm + split. One warp per (token, head).
// q,k,v -> [BH, N, D] row-major, coalesced, tf32-rounded. q gets *D^-0.5.
// ---------------------------------------------------------------------------
__global__ __launch_bounds__(384) void ln_split_k(
    const float* __restrict__ qkv,
    const float* __restrict__ qg, const float* __restrict__ qb,
    const float* __restrict__ kg, const float* __restrict__ kb,
    float* __restrict__ Qo, float* __restrict__ Ko, float* __restrict__ Vo)
{
    const int token = blockIdx.x;            // b*N + n
    const int b = token >> 11, n = token & 2047;
    const int h = threadIdx.x >> 5, lane = threadIdx.x & 31;
    const float* row = qkv + (size_t)token * QKVC + h * 64;
    const size_t base = ((size_t)(b * Hh + h) * Nn + n) * 64;

    // ---- q ----
    {
        float x0 = row[lane], x1 = row[lane + 32];
        float s = x0 + x1, sq = x0 * x0 + x1 * x1;
        #pragma unroll
        for (int off = 16; off; off >>= 1) {
            s  += __shfl_xor_sync(0xffffffffu, s,  off);
            sq += __shfl_xor_sync(0xffffffffu, sq, off);
        }
        float mean = s * (1.f / 64.f);
        float var  = sq * (1.f / 64.f) - mean * mean;
        float rstd = rsqrtf(var + 1e-5f);
        Qo[base + lane] =
            to_tf32(((x0 - mean) * rstd * qg[lane] + qb[lane]) * 0.125f);
        Qo[base + lane + 32] =
            to_tf32(((x1 - mean) * rstd * qg[lane + 32] + qb[lane + 32]) * 0.125f);
    }
    // ---- k ----
    {
        float x0 = row[768 + lane], x1 = row[768 + lane + 32];
        float s = x0 + x1, sq = x0 * x0 + x1 * x1;
        #pragma unroll
        for (int off = 16; off; off >>= 1) {
            s  += __shfl_xor_sync(0xffffffffu, s,  off);
            sq += __shfl_xor_sync(0xffffffffu, sq, off);
        }
        float mean = s * (1.f / 64.f);
        float var  = sq * (1.f / 64.f) - mean * mean;
        float rstd = rsqrtf(var + 1e-5f);
        Ko[base + lane] =
            to_tf32((x0 - mean) * rstd * kg[lane] + kb[lane]);
        Ko[base + lane + 32] =
            to_tf32((x1 - mean) * rstd * kg[lane + 32] + kb[lane + 32]);
    }
    // ---- v (row-major copy, tf32) ----
    Vo[base + lane]      = to_tf32(row[1536 + lane]);
    Vo[base + lane + 32] = to_tf32(row[1536 + lane + 32]);
}

// ---------------------------------------------------------------------------
// Flash attention via mma.sync tf32, cp.async 2-stage K/V pipeline.
// Q-tile 128 rows, kv-tile 64, 256 thr (8 warps); warp w: q rows w*16..+15.
// Q,K,V all [BH,N,D] row-major tf32. O out [BH,N,D] tf32-rounded.
// Smem floats: Qs[128][68] Ps[128][68] Ks{2}[64][68] Vs{2}[64][72] = 35328
//   (141312 B dynamic).
// ---------------------------------------------------------------------------
#define QS_OFF 0
#define PS_OFF 8704
#define KS_OFF(s) (17408 + (s) * 4352)
#define VS_OFF(s) (26112 + (s) * 4608)

__global__ __launch_bounds__(256) void attn_ca(
    const float* __restrict__ Qg, const float* __restrict__ Kg,
    const float* __restrict__ Vg, float* __restrict__ Og)
{
    extern __shared__ float sg[];
    const uint32_t sb = smem_u32(sg);

    const int tid = threadIdx.x, lane = tid & 31, w = tid >> 5;
    const int g = lane >> 2, tg = lane & 3;
    const int bh = blockIdx.y, q0 = blockIdx.x * 128;

    const float* Qp = Qg + ((size_t)bh * Nn + q0) * 64;
    const float* Kp = Kg + (size_t)bh * Nn * 64;
    const float* Vp = Vg + (size_t)bh * Nn * 64;

    auto issueKV = [&](int it, int s) {
        const int k0 = it * 64;
        #pragma unroll
        for (int i = 0; i < 4; i++) {
            int idx = tid + i * 256;
            int row = idx >> 4, c4 = (idx & 15) * 4;
            cp16(sb + (KS_OFF(s) + row * 68 + c4) * 4,
                 Kp + (size_t)(k0 + row) * 64 + c4);
            cp16(sb + (VS_OFF(s) + row * 72 + c4) * 4,
                 Vp + (size_t)(k0 + row) * 64 + c4);
        }
        CP_COMMIT();
    };

    // prologue: Q tile + K/V tile 0 (joined into commit group 0)
    #pragma unroll
    for (int i = 0; i < 8; i++) {
        int idx = tid + i * 256;
        int row = idx >> 4, c4 = (idx & 15) * 4;
        cp16(sb + (QS_OFF + row * 68 + c4) * 4, Qp + (size_t)row * 64 + c4);
    }
    issueKV(0, 0);

    float mrow0 = -CUDART_INF_F, mrow1 = -CUDART_INF_F;
    float lrow0 = 0.f, lrow1 = 0.f;
    float o[8][4];
    #pragma unroll
    for (int i = 0; i < 8; i++)
        #pragma unroll
        for (int j = 0; j < 4; j++) o[i][j] = 0.f;

    for (int it = 0; it < 32; ++it) {
        if (it + 1 < 32) { issueKV(it + 1, (it + 1) & 1); CP_WAIT(1); }
        else             { CP_WAIT(0); }
        __syncthreads();

        const float* Qs = sg + QS_OFF;
        const float* Ks = sg + KS_OFF(it & 1);
        const float* Vs = sg + VS_OFF(it & 1);
        float* Ps = sg + PS_OFF;

        // ---- S = Q K^T ----
        float s[8][4];
        #pragma unroll
        for (int i = 0; i < 8; i++)
            #pragma unroll
            for (int j = 0; j < 4; j++) s[i][j] = 0.f;

        #pragma unroll
        for (int ks = 0; ks < 8; ks++) {
            uint32_t aq[4];
            const float* ab = Qs + (w * 16 + g) * 68 + ks * 8 + tg;
            aq[0] = fu(ab[0]);
            aq[1] = fu(ab[8 * 68]);
            aq[2] = fu(ab[4]);
            aq[3] = fu(ab[8 * 68 + 4]);
            #pragma unroll
            for (int nt = 0; nt < 8; nt++) {
                uint32_t b[2];
                const float* bb = Ks + (nt * 8 + g) * 68 + ks * 8 + tg;
                b[0] = fu(bb[0]);
                b[1] = fu(bb[4]);
                mma8(s[nt], aq, b);
            }
        }

        // ---- online softmax ----
        float mx0 = -CUDART_INF_F, mx1 = -CUDART_INF_F;
        #pragma unroll
        for (int nt = 0; nt < 8; nt++) {
            mx0 = fmaxf(mx0, fmaxf(s[nt][0], s[nt][1]));
            mx1 = fmaxf(mx1, fmaxf(s[nt][2], s[nt][3]));
        }
        mx0 = fmaxf(mx0, __shfl_xor_sync(0xffffffffu, mx0, 1));
        mx0 = fmaxf(mx0, __shfl_xor_sync(0xffffffffu, mx0, 2));
        mx1 = fmaxf(mx1, __shfl_xor_sync(0xffffffffu, mx1, 1));
        mx1 = fmaxf(mx1, __shfl_xor_sync(0xffffffffu, mx1, 2));

        const float mn0 = fmaxf(mrow0, mx0), mn1 = fmaxf(mrow1, mx1);
        const float cr0 = __expf(mrow0 - mn0), cr1 = __expf(mrow1 - mn1);
        float ps0 = 0.f, ps1 = 0.f;
        #pragma unroll
        for (int nt = 0; nt < 8; nt++) {
            float p00 = __expf(s[nt][0] - mn0), p01 = __expf(s[nt][1] - mn0);
            float p10 = __expf(s[nt][2] - mn1), p11 = __expf(s[nt][3] - mn1);
            ps0 += p00 + p01;
            ps1 += p10 + p11;
            float2 w0 = { to_tf32(p00), to_tf32(p01) };
            float2 w1 = { to_tf32(p10), to_tf32(p11) };
            *(float2*)(Ps + (w * 16 + g) * 68 + nt * 8 + 2 * tg)     = w0;
            *(float2*)(Ps + (w * 16 + g + 8) * 68 + nt * 8 + 2 * tg) = w1;
        }
        ps0 += __shfl_xor_sync(0xffffffffu, ps0, 1);
        ps0 += __shfl_xor_sync(0xffffffffu, ps0, 2);
        ps1 += __shfl_xor_sync(0xffffffffu, ps1, 1);
        ps1 += __shfl_xor_sync(0xffffffffu, ps1, 2);
        lrow0 = lrow0 * cr0 + ps0;
        lrow1 = lrow1 * cr1 + ps1;
        mrow0 = mn0; mrow1 = mn1;
        #pragma unroll
        for (int nt = 0; nt < 8; nt++) {
            o[nt][0] *= cr0; o[nt][1] *= cr0;
            o[nt][2] *= cr1; o[nt][3] *= cr1;
        }
        __syncwarp();   // Ps rows are warp-private: warp-scope fence suffices

        // ---- O += P V  (B-frag from row-major Vs[kv][72]) ----
        #pragma unroll
        for (int ks = 0; ks < 8; ks++) {
            uint32_t ap[4];
            const float* pb = Ps + (w * 16 + g) * 68 + ks * 8 + tg;
            ap[0] = fu(pb[0]);
            ap[1] = fu(pb[8 * 68]);
            ap[2] = fu(pb[4]);
            ap[3] = fu(pb[8 * 68 + 4]);
            #pragma unroll
            for (int nt = 0; nt < 8; nt++) {
                uint32_t b[2];
                const float* vb = Vs + (ks * 8 + tg) * 72 + nt * 8 + g;
                b[0] = fu(vb[0]);
                b[1] = fu(vb[4 * 72]);
                mma8(o[nt], ap, b);
            }
        }
        __syncthreads();   // release K/V buffer for next issue
    }

    // ---- epilogue (tf32-rounded: feeds proj GEMM) ----
    const float inv0 = 1.f / lrow0, inv1 = 1.f / lrow1;
    const int r0 = q0 + w * 16 + g;
    #pragma unroll
    for (int nt = 0; nt < 8; nt++) {
        const int col = nt * 8 + 2 * tg;
        float2 v0 = { to_tf32(o[nt][0] * inv0), to_tf32(o[nt][1] * inv0) };
        float2 v1 = { to_tf32(o[nt][2] * inv1), to_tf32(o[nt][3] * inv1) };
        *(float2*)(Og + ((size_t)bh * Nn + r0) * 64 + col) = v0;
        *(float2*)(Og + ((size_t)bh * Nn + r0 + 8) * 64 + col) = v1;
    }
}

// ---------------------------------------------------------------------------
extern "C" void kernel_launch(void* const* d_in, const int* in_sizes, int n_in,
                              void* d_out, int out_size)
{
    const float* x       = (const float*)d_in[0];
    const float* w_qkv   = (const float*)d_in[1];
    const float* q_gamma = (const float*)d_in[2];
    const float* q_beta  = (const float*)d_in[3];
    const float* k_gamma = (const float*)d_in[4];
    const float* k_beta  = (const float*)d_in[5];
    const float* w_proj  = (const float*)d_in[6];
    const float* b_proj  = (const float*)d_in[7];
    float* out = (float*)d_out;

    float *qkv, *q, *k, *v, *o, *xr, *wq, *wp;
    cudaGetSymbolAddress((void**)&qkv, g_qkv);
    cudaGetSymbolAddress((void**)&q,   g_q);
    cudaGetSymbolAddress((void**)&k,   g_k);
    cudaGetSymbolAddress((void**)&v,   g_v);
    cudaGetSymbolAddress((void**)&o,   g_o);
    cudaGetSymbolAddress((void**)&xr,  g_x);
    cudaGetSymbolAddress((void**)&wq,  g_wq);
    cudaGetSymbolAddress((void**)&wp,  g_wp);

    const int GEMM_SMEM = 71680;
    const int ATTN_SMEM = 141312;
    cudaFuncSetAttribute(gemm_ca<false, false>,
                         cudaFuncAttributeMaxDynamicSharedMemorySize, GEMM_SMEM);
    cudaFuncSetAttribute(gemm_ca<true, true>,
                         cudaFuncAttributeMaxDynamicSharedMemorySize, GEMM_SMEM);
    cudaFuncSetAttribute(attn_ca,
                         cudaFuncAttributeMaxDynamicSharedMemorySize, ATTN_SMEM);

    // 0) tf32 pre-round of GEMM inputs
    {
        int n4x = Mm * Cc / 4;        // 1572864
        int n4q = Cc * QKVC / 4;      // 442368
        int n4p = Cc * Cc / 4;        // 147456
        round4_k<<<(n4x + 255) / 256, 256>>>((const float4*)x, (float4*)xr, n4x);
        round4_k<<<(n4q + 255) / 256, 256>>>((const float4*)w_qkv, (float4*)wq, n4q);
        round4_k<<<(n4p + 255) / 256, 256>>>((const float4*)w_proj, (float4*)wp, n4p);
    }

    // 1) qkv = x @ w_qkv
    gemm_ca<false, false><<<dim3(QKVC / 128, Mm / 128), 256, GEMM_SMEM>>>(
        xr, wq, nullptr, qkv, QKVC, Cc);

    // 2) LayerNorm q,k (+scale q); q,k,v row-major tf32
    ln_split_k<<<Mm, 384>>>(qkv, q_gamma, q_beta, k_gamma, k_beta, q, k, v);

    // 3) flash attention
    attn_ca<<<dim3(Nn / 128, BH), 256, ATTN_SMEM>>>(q, k, v, o);

    // 4) out = attn_out @ w_proj + b
    gemm_ca<true, true><<<dim3(Cc / 128, Mm / 128), 256, GEMM_SMEM>>>(
        o, wp, b_proj, out, Cc, Cc);
}

// round 7
// speedup vs baseline: 3.5072x; 1.0910x over previous
#include <cuda_runtime.h>
#include <cuda_bf16.h>
#include <math_constants.h>
#include <cstdint>

// Problem constants
#define Bb 4
#define Nn 2048
#define Cc 768
#define Hh 12
#define Dd 64
#define Mm (Bb * Nn)        // 8192
#define QKVC (3 * Cc)       // 2304
#define BH (Bb * Hh)        // 48

// ---------------- scratch (device globals; no allocation allowed) ----------
__device__ __align__(256) float g_q[(size_t)BH * Nn * Dd]; // [BH,N,D] tf32
__device__ __align__(256) float g_k[(size_t)BH * Nn * Dd]; // [BH,N,D] tf32
__device__ __align__(256) float g_v[(size_t)BH * Nn * Dd]; // [BH,N,D] tf32
__device__ __align__(256) float g_o[(size_t)BH * Nn * Dd]; // [BH,N,D] tf32
__device__ __align__(256) float g_x[(size_t)Mm * Cc];      // tf32 x
__device__ __align__(256) float g_wq[(size_t)Cc * QKVC];   // tf32 w_qkv
__device__ __align__(256) float g_wp[(size_t)Cc * Cc];     // tf32 w_proj

// ===========================================================================
// helpers
// ===========================================================================
__device__ __forceinline__ float to_tf32(float x) {
    uint32_t u;
    asm("cvt.rna.tf32.f32 %0, %1;" : "=r"(u) : "f"(x));
    return __uint_as_float(u);
}
__device__ __forceinline__ void mma8(float* d, const uint32_t* a, const uint32_t* b) {
    asm volatile(
        "mma.sync.aligned.m16n8k8.row.col.f32.tf32.tf32.f32 "
        "{%0,%1,%2,%3}, {%4,%5,%6,%7}, {%8,%9}, {%0,%1,%2,%3};\n"
        : "+f"(d[0]), "+f"(d[1]), "+f"(d[2]), "+f"(d[3])
        : "r"(a[0]), "r"(a[1]), "r"(a[2]), "r"(a[3]),
          "r"(b[0]), "r"(b[1]));
}
__device__ __forceinline__ uint32_t fu(float x) { return __float_as_uint(x); }
__device__ __forceinline__ uint32_t smem_u32(const void* p) {
    uint32_t a;
    asm("{ .reg .u64 t; cvta.to.shared.u64 t, %1; cvt.u32.u64 %0, t; }"
        : "=r"(a) : "l"(p));
    return a;
}
__device__ __forceinline__ void cp16(uint32_t dst, const void* src) {
    asm volatile("cp.async.cg.shared.global [%0], [%1], 16;\n"
                 :: "r"(dst), "l"(src));
}
#define CP_COMMIT() asm volatile("cp.async.commit_group;\n" ::: "memory")
#define CP_WAIT(N)  asm volatile("cp.async.wait_group %0;\n" :: "n"(N) : "memory")

// ===========================================================================
// tf32 pre-round pass (elementwise, float4)
// ===========================================================================
__global__ void round4_k(const float4* __restrict__ in, float4* __restrict__ out,
                         int n4)
{
    int i = blockIdx.x * blockDim.x + threadIdx.x;
    if (i < n4) {
        float4 v = in[i];
        v.x = to_tf32(v.x); v.y = to_tf32(v.y);
        v.z = to_tf32(v.z); v.w = to_tf32(v.w);
        out[i] = v;
    }
}

// ===========================================================================
// GEMM smem layout (3 stages): As[128][36] Bs[32][136] per stage.
// AS(s)=s*4608, BS(s)=13824+s*4352; total 26880 floats = 107520 B.
// ===========================================================================
#define G_AS(s) ((s) * 4608)
#define G_BS(s) (13824 + (s) * 4352)
#define G_SMEM_B 107520

// ---------------------------------------------------------------------------
// fused qkv GEMM + LayerNorm + split. C-tile 128x128 (= 2 complete heads).
// A = tf32 x [M,768], B = tf32 w_qkv [768,2304]. Outputs q,k,v in [BH,N,D].
// ---------------------------------------------------------------------------
__global__ __launch_bounds__(256, 2) void gemm_qkv_ln(
    const float* __restrict__ A, const float* __restrict__ Bm,
    const float* __restrict__ qg, const float* __restrict__ qb,
    const float* __restrict__ kg, const float* __restrict__ kb,
    float* __restrict__ Qo, float* __restrict__ Ko, float* __restrict__ Vo)
{
    extern __shared__ float sg[];
    const uint32_t sb = smem_u32(sg);

    const int tid  = threadIdx.x;
    const int lane = tid & 31, wid = tid >> 5;
    const int g = lane >> 2, tg = lane & 3;
    const int wm = (wid & 1) * 64, wn = (wid >> 1) * 32;
    const int m0 = blockIdx.y * 128, n0 = blockIdx.x * 128;
    const int K = Cc, Nc = QKVC;

    float acc[4][4][4];
    #pragma unroll
    for (int i = 0; i < 4; i++)
        #pragma unroll
        for (int j = 0; j < 4; j++)
            #pragma unroll
            for (int r = 0; r < 4; r++) acc[i][j][r] = 0.f;

    auto issue = [&](int it, int s) {
        const int k0 = it * 32;
        #pragma unroll
        for (int i = 0; i < 4; i++) {
            int idx = tid + i * 256;
            int row = idx >> 3, kk = (idx & 7) * 4;
            cp16(sb + (G_AS(s) + row * 36 + kk) * 4,
                 A + (size_t)(m0 + row) * K + k0 + kk);
        }
        #pragma unroll
        for (int i = 0; i < 4; i++) {
            int idx = tid + i * 256;
            int kr = idx >> 5, n4 = (idx & 31) * 4;
            cp16(sb + (G_BS(s) + kr * 136 + n4) * 4,
                 Bm + (size_t)(k0 + kr) * Nc + n0 + n4);
        }
        CP_COMMIT();
    };

    const int ITERS = K / 32;          // 24
    issue(0, 0); issue(1, 1); issue(2, 2);
    CP_WAIT(2);
    __syncthreads();

    for (int it = 0; it < ITERS; ++it) {
        const float* As = sg + G_AS(it % 3);
        const float* Bs = sg + G_BS(it % 3);
        #pragma unroll
        for (int ks = 0; ks < 4; ks++) {
            const int kk = ks * 8;
            uint32_t afr[4][4], bfr[4][2];
            #pragma unroll
            for (int mt = 0; mt < 4; mt++) {
                const float* ab = As + (wm + mt * 16 + g) * 36 + kk + tg;
                afr[mt][0] = fu(ab[0]);
                afr[mt][1] = fu(ab[8 * 36]);
                afr[mt][2] = fu(ab[4]);
                afr[mt][3] = fu(ab[8 * 36 + 4]);
            }
            #pragma unroll
            for (int nt = 0; nt < 4; nt++) {
                const float* bb = Bs + (kk + tg) * 136 + wn + nt * 8 + g;
                bfr[nt][0] = fu(bb[0]);
                bfr[nt][1] = fu(bb[4 * 136]);
            }
            #pragma unroll
            for (int mt = 0; mt < 4; mt++)
                #pragma unroll
                for (int nt = 0; nt < 4; nt++)
                    mma8(acc[mt][nt], afr[mt], bfr[nt]);
        }
        __syncthreads();
        if (it + 3 < ITERS)      { issue(it + 3, (it + 3) % 3); CP_WAIT(2); }
        else if (it + 2 < ITERS) { CP_WAIT(1); }
        else if (it + 1 < ITERS) { CP_WAIT(0); }
        __syncthreads();
    }

    // ---- stage accumulators into Cs[128][132] (reuses pipeline smem) ----
    float* Cs = sg;
    #pragma unroll
    for (int mt = 0; mt < 4; mt++) {
        int row = wm + mt * 16 + g;
        #pragma unroll
        for (int nt = 0; nt < 4; nt++) {
            int col = wn + nt * 8 + 2 * tg;
            *(float2*)(Cs + row * 132 + col) =
                make_float2(acc[mt][nt][0], acc[mt][nt][1]);
            *(float2*)(Cs + (row + 8) * 132 + col) =
                make_float2(acc[mt][nt][2], acc[mt][nt][3]);
        }
    }
    __syncthreads();

    // ---- LN / split: 8 lanes per row-head, 4 row-heads per warp per pass ----
    const int sect  = n0 / 768;          // 0=q, 1=k, 2=v
    const int hbase = (n0 % 768) / 64;   // head base (2 heads per tile)
    const int oct = lane >> 3, li = lane & 7;
    float* outp = (sect == 0) ? Qo : (sect == 1) ? Ko : Vo;
    const float* gam = (sect == 0) ? qg : kg;
    const float* bet = (sect == 0) ? qb : kb;
    const float qs = (sect == 0) ? 0.125f : 1.0f;

    float4 ga0, ga1, be0, be1;
    if (sect < 2) {
        ga0 = *(const float4*)(gam + li * 8);
        ga1 = *(const float4*)(gam + li * 8 + 4);
        be0 = *(const float4*)(bet + li * 8);
        be1 = *(const float4*)(bet + li * 8 + 4);
    }

    for (int itr = 0; itr < 8; itr++) {
        int rh = wid * 32 + itr * 4 + oct;      // 0..255
        int row = rh >> 1, hh = rh & 1;
        const float* src = Cs + row * 132 + hh * 64 + li * 8;
        float4 f0 = *(const float4*)(src);
        float4 f1 = *(const float4*)(src + 4);
        int token = m0 + row;
        int b = token >> 11, n = token & 2047;
        float* dst = outp +
            (((size_t)(b * Hh + hbase + hh) * Nn + n) << 6) + li * 8;
        if (sect < 2) {
            float s8 = f0.x + f0.y + f0.z + f0.w + f1.x + f1.y + f1.z + f1.w;
            float q8 = f0.x*f0.x + f0.y*f0.y + f0.z*f0.z + f0.w*f0.w +
                       f1.x*f1.x + f1.y*f1.y + f1.z*f1.z + f1.w*f1.w;
            #pragma unroll
            for (int off = 1; off <= 4; off <<= 1) {
                s8 += __shfl_xor_sync(0xffffffffu, s8, off);
                q8 += __shfl_xor_sync(0xffffffffu, q8, off);
            }
            float mean = s8 * (1.f / 64.f);
            float var  = q8 * (1.f / 64.f) - mean * mean;
            float rstd = rsqrtf(var + 1e-5f);
            f0.x = to_tf32(((f0.x - mean) * rstd * ga0.x + be0.x) * qs);
            f0.y = to_tf32(((f0.y - mean) * rstd * ga0.y + be0.y) * qs);
            f0.z = to_tf32(((f0.z - mean) * rstd * ga0.z + be0.z) * qs);
            f0.w = to_tf32(((f0.w - mean) * rstd * ga0.w + be0.w) * qs);
            f1.x = to_tf32(((f1.x - mean) * rstd * ga1.x + be1.x) * qs);
            f1.y = to_tf32(((f1.y - mean) * rstd * ga1.y + be1.y) * qs);
            f1.z = to_tf32(((f1.z - mean) * rstd * ga1.z + be1.z) * qs);
            f1.w = to_tf32(((f1.w - mean) * rstd * ga1.w + be1.w) * qs);
        } else {
            f0.x = to_tf32(f0.x); f0.y = to_tf32(f0.y);
            f0.z = to_tf32(f0.z); f0.w = to_tf32(f0.w);
            f1.x = to_tf32(f1.x); f1.y = to_tf32(f1.y);
            f1.z = to_tf32(f1.z); f1.w = to_tf32(f1.w);
        }
        *(float4*)(dst)     = f0;
        *(float4*)(dst + 4) = f1;
    }
}

// ===========================================================================
// proj GEMM (3-stage cp.async). C = A@B + bias; A remapped from [BH,N,D].
// ===========================================================================
__global__ __launch_bounds__(256, 2) void gemm_proj(
    const float* __restrict__ A, const float* __restrict__ Bm,
    const float* __restrict__ bias, float* __restrict__ C)
{
    extern __shared__ float sg[];
    const uint32_t sb = smem_u32(sg);

    const int tid  = threadIdx.x;
    const int lane = tid & 31, wid = tid >> 5;
    const int g = lane >> 2, tg = lane & 3;
    const int wm = (wid & 1) * 64, wn = (wid >> 1) * 32;
    const int m0 = blockIdx.y * 128, n0 = blockIdx.x * 128;
    const int K = Cc, Nc = Cc;

    float acc[4][4][4];
    #pragma unroll
    for (int i = 0; i < 4; i++)
        #pragma unroll
        for (int j = 0; j < 4; j++)
            #pragma unroll
            for (int r = 0; r < 4; r++) acc[i][j][r] = 0.f;

    auto issue = [&](int it, int s) {
        const int k0 = it * 32;
        #pragma unroll
        for (int i = 0; i < 4; i++) {
            int idx = tid + i * 256;
            int row = idx >> 3, kk = (idx & 7) * 4;
            int gk = k0 + kk;
            int h = gk >> 6, d0 = gk & 63;
            int gm = m0 + row, b = gm >> 11, n = gm & 2047;
            cp16(sb + (G_AS(s) + row * 36 + kk) * 4,
                 A + (((size_t)(b * Hh + h) * Nn + n) << 6) + d0);
        }
        #pragma unroll
        for (int i = 0; i < 4; i++) {
            int idx = tid + i * 256;
            int kr = idx >> 5, n4 = (idx & 31) * 4;
            cp16(sb + (G_BS(s) + kr * 136 + n4) * 4,
                 Bm + (size_t)(k0 + kr) * Nc + n0 + n4);
        }
        CP_COMMIT();
    };

    const int ITERS = K / 32;          // 24
    issue(0, 0); issue(1, 1); issue(2, 2);
    CP_WAIT(2);
    __syncthreads();

    for (int it = 0; it < ITERS; ++it) {
        const float* As = sg + G_AS(it % 3);
        const float* Bs = sg + G_BS(it % 3);
        #pragma unroll
        for (int ks = 0; ks < 4; ks++) {
            const int kk = ks * 8;
            uint32_t afr[4][4], bfr[4][2];
            #pragma unroll
            for (int mt = 0; mt < 4; mt++) {
                const float* ab = As + (wm + mt * 16 + g) * 36 + kk + tg;
                afr[mt][0] = fu(ab[0]);
                afr[mt][1] = fu(ab[8 * 36]);
                afr[mt][2] = fu(ab[4]);
                afr[mt][3] = fu(ab[8 * 36 + 4]);
            }
            #pragma unroll
            for (int nt = 0; nt < 4; nt++) {
                const float* bb = Bs + (kk + tg) * 136 + wn + nt * 8 + g;
                bfr[nt][0] = fu(bb[0]);
                bfr[nt][1] = fu(bb[4 * 136]);
            }
            #pragma unroll
            for (int mt = 0; mt < 4; mt++)
                #pragma unroll
                for (int nt = 0; nt < 4; nt++)
                    mma8(acc[mt][nt], afr[mt], bfr[nt]);
        }
        __syncthreads();
        if (it + 3 < ITERS)      { issue(it + 3, (it + 3) % 3); CP_WAIT(2); }
        else if (it + 2 < ITERS) { CP_WAIT(1); }
        else if (it + 1 < ITERS) { CP_WAIT(0); }
        __syncthreads();
    }

    #pragma unroll
    for (int mt = 0; mt < 4; mt++) {
        const int r0 = m0 + wm + mt * 16 + g;
        #pragma unroll
        for (int nt = 0; nt < 4; nt++) {
            const int col = n0 + wn + nt * 8 + 2 * tg;
            float bx = bias[col], by = bias[col + 1];
            float2 v0 = { acc[mt][nt][0] + bx, acc[mt][nt][1] + by };
            float2 v1 = { acc[mt][nt][2] + bx, acc[mt][nt][3] + by };
            *(float2*)(C + (size_t)r0 * Nc + col) = v0;
            *(float2*)(C + (size_t)(r0 + 8) * Nc + col) = v1;
        }
    }
}

// ===========================================================================
// Flash attention, mma.sync tf32, 3-stage cp.async K/V pipeline, hoisted
// Q fragments. Q-tile 128 rows, kv-tile 64, 256 thr (8 warps).
// Smem floats: Qs[128][68] Ps[128][68] Ks{3}[64][68] Vs{3}[64][72]
//   = 44288 floats = 177152 B.
// ===========================================================================
#define QS_OFF 0
#define PS_OFF 8704
#define KS_OFF(s) (17408 + (s) * 4352)
#define VS_OFF(s) (30464 + (s) * 4608)
#define ATTN_SMEM_B 177152

__global__ __launch_bounds__(256) void attn_ca(
    const float* __restrict__ Qg, const float* __restrict__ Kg,
    const float* __restrict__ Vg, float* __restrict__ Og)
{
    extern __shared__ float sg[];
    const uint32_t sb = smem_u32(sg);

    const int tid = threadIdx.x, lane = tid & 31, w = tid >> 5;
    const int g = lane >> 2, tg = lane & 3;
    const int bh = blockIdx.y, q0 = blockIdx.x * 128;

    const float* Qp = Qg + ((size_t)bh * Nn + q0) * 64;
    const float* Kp = Kg + (size_t)bh * Nn * 64;
    const float* Vp = Vg + (size_t)bh * Nn * 64;

    auto issueKV = [&](int it, int s) {
        const int k0 = it * 64;
        #pragma unroll
        for (int i = 0; i < 4; i++) {
            int idx = tid + i * 256;
            int row = idx >> 4, c4 = (idx & 15) * 4;
            cp16(sb + (KS_OFF(s) + row * 68 + c4) * 4,
                 Kp + (size_t)(k0 + row) * 64 + c4);
            cp16(sb + (VS_OFF(s) + row * 72 + c4) * 4,
                 Vp + (size_t)(k0 + row) * 64 + c4);
        }
        CP_COMMIT();
    };

    // prologue: {Q + KV0} as group0, KV1, KV2
    #pragma unroll
    for (int i = 0; i < 8; i++) {
        int idx = tid + i * 256;
        int row = idx >> 4, c4 = (idx & 15) * 4;
        cp16(sb + (QS_OFF + row * 68 + c4) * 4, Qp + (size_t)row * 64 + c4);
    }
    issueKV(0, 0);
    issueKV(1, 1);
    issueKV(2, 2);
    CP_WAIT(2);
    __syncthreads();

    // hoist Q fragments (loop-invariant)
    uint32_t qf[8][4];
    {
        const float* Qs = sg + QS_OFF;
        #pragma unroll
        for (int ks = 0; ks < 8; ks++) {
            const float* ab = Qs + (w * 16 + g) * 68 + ks * 8 + tg;
            qf[ks][0] = fu(ab[0]);
            qf[ks][1] = fu(ab[8 * 68]);
            qf[ks][2] = fu(ab[4]);
            qf[ks][3] = fu(ab[8 * 68 + 4]);
        }
    }

    float mrow0 = -CUDART_INF_F, mrow1 = -CUDART_INF_F;
    float lrow0 = 0.f, lrow1 = 0.f;
    float o[8][4];
    #pragma unroll
    for (int i = 0; i < 8; i++)
        #pragma unroll
        for (int j = 0; j < 4; j++) o[i][j] = 0.f;

    const int ITERS = 32;
    for (int it = 0; it < ITERS; ++it) {
        const float* Ks = sg + KS_OFF(it % 3);
        const float* Vs = sg + VS_OFF(it % 3);
        float* Ps = sg + PS_OFF;

        // ---- S = Q K^T ----
        float s[8][4];
        #pragma unroll
        for (int i = 0; i < 8; i++)
            #pragma unroll
            for (int j = 0; j < 4; j++) s[i][j] = 0.f;

        #pragma unroll
        for (int ks = 0; ks < 8; ks++) {
            #pragma unroll
            for (int nt = 0; nt < 8; nt++) {
                uint32_t b[2];
                const float* bb = Ks + (nt * 8 + g) * 68 + ks * 8 + tg;
                b[0] = fu(bb[0]);
                b[1] = fu(bb[4]);
                mma8(s[nt], qf[ks], b);
            }
        }

        // ---- online softmax ----
        float mx0 = -CUDART_INF_F, mx1 = -CUDART_INF_F;
        #pragma unroll
        for (int nt = 0; nt < 8; nt++) {
            mx0 = fmaxf(mx0, fmaxf(s[nt][0], s[nt][1]));
            mx1 = fmaxf(mx1, fmaxf(s[nt][2], s[nt][3]));
        }
        mx0 = fmaxf(mx0, __shfl_xor_sync(0xffffffffu, mx0, 1));
        mx0 = fmaxf(mx0, __shfl_xor_sync(0xffffffffu, mx0, 2));
        mx1 = fmaxf(mx1, __shfl_xor_sync(0xffffffffu, mx1, 1));
        mx1 = fmaxf(mx1, __shfl_xor_sync(0xffffffffu, mx1, 2));

        const float mn0 = fmaxf(mrow0, mx0), mn1 = fmaxf(mrow1, mx1);
        const float cr0 = __expf(mrow0 - mn0), cr1 = __expf(mrow1 - mn1);
        float ps0 = 0.f, ps1 = 0.f;
        #pragma unroll
        for (int nt = 0; nt < 8; nt++) {
            float p00 = __expf(s[nt][0] - mn0), p01 = __expf(s[nt][1] - mn0);
            float p10 = __expf(s[nt][2] - mn1), p11 = __expf(s[nt][3] - mn1);
            ps0 += p00 + p01;
            ps1 += p10 + p11;
            float2 w0 = { to_tf32(p00), to_tf32(p01) };
            float2 w1 = { to_tf32(p10), to_tf32(p11) };
            *(float2*)(Ps + (w * 16 + g) * 68 + nt * 8 + 2 * tg)     = w0;
            *(float2*)(Ps + (w * 16 + g + 8) * 68 + nt * 8 + 2 * tg) = w1;
        }
        ps0 += __shfl_xor_sync(0xffffffffu, ps0, 1);
        ps0 += __shfl_xor_sync(0xffffffffu, ps0, 2);
        ps1 += __shfl_xor_sync(0xffffffffu, ps1, 1);
        ps1 += __shfl_xor_sync(0xffffffffu, ps1, 2);
        lrow0 = lrow0 * cr0 + ps0;
        lrow1 = lrow1 * cr1 + ps1;
        mrow0 = mn0; mrow1 = mn1;
        #pragma unroll
        for (int nt = 0; nt < 8; nt++) {
            o[nt][0] *= cr0; o[nt][1] *= cr0;
            o[nt][2] *= cr1; o[nt][3] *= cr1;
        }
        __syncwarp();   // Ps rows are warp-private

        // ---- O += P V ----
        #pragma unroll
        for (int ks = 0; ks < 8; ks++) {
            uint32_t ap[4];
            const float* pb = Ps + (w * 16 + g) * 68 + ks * 8 + tg;
            ap[0] = fu(pb[0]);
            ap[1] = fu(pb[8 * 68]);
            ap[2] = fu(pb[4]);
            ap[3] = fu(pb[8 * 68 + 4]);
            #pragma unroll
            for (int nt = 0; nt < 8; nt++) {
                uint32_t b[2];
                const float* vb = Vs + (ks * 8 + tg) * 72 + nt * 8 + g;
                b[0] = fu(vb[0]);
                b[1] = fu(vb[4 * 72]);
                mma8(o[nt], ap, b);
            }
        }
        __syncthreads();                      // all warps done with stage it%3
        if (it + 3 < ITERS)      { issueKV(it + 3, (it + 3) % 3); CP_WAIT(2); }
        else if (it + 2 < ITERS) { CP_WAIT(1); }
        else if (it + 1 < ITERS) { CP_WAIT(0); }
        __syncthreads();                      // stage (it+1)%3 visible
    }

    // ---- epilogue (tf32-rounded: feeds proj GEMM) ----
    const float inv0 = 1.f / lrow0, inv1 = 1.f / lrow1;
    const int r0 = q0 + w * 16 + g;
    #pragma unroll
    for (int nt = 0; nt < 8; nt++) {
        const int col = nt * 8 + 2 * tg;
        float2 v0 = { to_tf32(o[nt][0] * inv0), to_tf32(o[nt][1] * inv0) };
        float2 v1 = { to_tf32(o[nt][2] * inv1), to_tf32(o[nt][3] * inv1) };
        *(float2*)(Og + ((size_t)bh * Nn + r0) * 64 + col) = v0;
        *(float2*)(Og + ((size_t)bh * Nn + r0 + 8) * 64 + col) = v1;
    }
}

// ---------------------------------------------------------------------------
extern "C" void kernel_launch(void* const* d_in, const int* in_sizes, int n_in,
                              void* d_out, int out_size)
{
    const float* x       = (const float*)d_in[0];
    const float* w_qkv   = (const float*)d_in[1];
    const float* q_gamma = (const float*)d_in[2];
    const float* q_beta  = (const float*)d_in[3];
    const float* k_gamma = (const float*)d_in[4];
    const float* k_beta  = (const float*)d_in[5];
    const float* w_proj  = (const float*)d_in[6];
    const float* b_proj  = (const float*)d_in[7];
    float* out = (float*)d_out;

    float *q, *k, *v, *o, *xr, *wq, *wp;
    cudaGetSymbolAddress((void**)&q,  g_q);
    cudaGetSymbolAddress((void**)&k,  g_k);
    cudaGetSymbolAddress((void**)&v,  g_v);
    cudaGetSymbolAddress((void**)&o,  g_o);
    cudaGetSymbolAddress((void**)&xr, g_x);
    cudaGetSymbolAddress((void**)&wq, g_wq);
    cudaGetSymbolAddress((void**)&wp, g_wp);

    cudaFuncSetAttribute(gemm_qkv_ln,
                         cudaFuncAttributeMaxDynamicSharedMemorySize, G_SMEM_B);
    cudaFuncSetAttribute(gemm_proj,
                         cudaFuncAttributeMaxDynamicSharedMemorySize, G_SMEM_B);
    cudaFuncSetAttribute(attn_ca,
                         cudaFuncAttributeMaxDynamicSharedMemorySize, ATTN_SMEM_B);

    // 0) tf32 pre-round of GEMM inputs
    {
        int n4x = Mm * Cc / 4;
        int n4q = Cc * QKVC / 4;
        int n4p = Cc * Cc / 4;
        round4_k<<<(n4x + 255) / 256, 256>>>((const float4*)x, (float4*)xr, n4x);
        round4_k<<<(n4q + 255) / 256, 256>>>((const float4*)w_qkv, (float4*)wq, n4q);
        round4_k<<<(n4p + 255) / 256, 256>>>((const float4*)w_proj, (float4*)wp, n4p);
    }

    // 1) fused qkv GEMM + LayerNorm + split
    gemm_qkv_ln<<<dim3(QKVC / 128, Mm / 128), 256, G_SMEM_B>>>(
        xr, wq, q_gamma, q_beta, k_gamma, k_beta, q, k, v);

    // 2) flash attention
    attn_ca<<<dim3(Nn / 128, BH), 256, ATTN_SMEM_B>>>(q, k, v, o);

    // 3) out = attn_out @ w_proj + b
    gemm_proj<<<dim3(Cc / 128, Mm / 128), 256, G_SMEM_B>>>(
        o, wp, b_proj, out);
}

// round 8
// speedup vs baseline: 3.9182x; 1.1172x over previous
#include <cuda_runtime.h>
#include <cuda_bf16.h>
#include <math_constants.h>
#include <cstdint>

// Problem constants
#define Bb 4
#define Nn 2048
#define Cc 768
#define Hh 12
#define Dd 64
#define Mm (Bb * Nn)        // 8192
#define QKVC (3 * Cc)       // 2304
#define BH (Bb * Hh)        // 48

// ---------------- scratch (device globals; no allocation allowed) ----------
__device__ __align__(256) float g_q[(size_t)BH * Nn * Dd]; // [BH,N,D] tf32
__device__ __align__(256) float g_k[(size_t)BH * Nn * Dd]; // [BH,N,D] tf32
__device__ __align__(256) float g_v[(size_t)BH * Nn * Dd]; // [BH,N,D] tf32
__device__ __align__(256) float g_o[(size_t)BH * Nn * Dd]; // [BH,N,D] tf32
__device__ __align__(256) float g_x[(size_t)Mm * Cc];      // tf32 x
__device__ __align__(256) float g_wq[(size_t)Cc * QKVC];   // tf32 w_qkv
__device__ __align__(256) float g_wp[(size_t)Cc * Cc];     // tf32 w_proj

// ===========================================================================
// helpers
// ===========================================================================
__device__ __forceinline__ float to_tf32(float x) {
    uint32_t u;
    asm("cvt.rna.tf32.f32 %0, %1;" : "=r"(u) : "f"(x));
    return __uint_as_float(u);
}
__device__ __forceinline__ void mma8(float* d, const uint32_t* a, const uint32_t* b) {
    asm volatile(
        "mma.sync.aligned.m16n8k8.row.col.f32.tf32.tf32.f32 "
        "{%0,%1,%2,%3}, {%4,%5,%6,%7}, {%8,%9}, {%0,%1,%2,%3};\n"
        : "+f"(d[0]), "+f"(d[1]), "+f"(d[2]), "+f"(d[3])
        : "r"(a[0]), "r"(a[1]), "r"(a[2]), "r"(a[3]),
          "r"(b[0]), "r"(b[1]));
}
__device__ __forceinline__ uint32_t fu(float x) { return __float_as_uint(x); }
__device__ __forceinline__ uint32_t smem_u32(const void* p) {
    uint32_t a;
    asm("{ .reg .u64 t; cvta.to.shared.u64 t, %1; cvt.u32.u64 %0, t; }"
        : "=r"(a) : "l"(p));
    return a;
}
__device__ __forceinline__ void cp16(uint32_t dst, const void* src) {
    asm volatile("cp.async.cg.shared.global [%0], [%1], 16;\n"
                 :: "r"(dst), "l"(src));
}
#define CP_COMMIT() asm volatile("cp.async.commit_group;\n" ::: "memory")
#define CP_WAIT(N)  asm volatile("cp.async.wait_group %0;\n" :: "n"(N) : "memory")

// ===========================================================================
// tf32 pre-round pass (elementwise, float4)
// ===========================================================================
__global__ void round4_k(const float4* __restrict__ in, float4* __restrict__ out,
                         int n4)
{
    int i = blockIdx.x * blockDim.x + threadIdx.x;
    if (i < n4) {
        float4 v = in[i];
        v.x = to_tf32(v.x); v.y = to_tf32(v.y);
        v.z = to_tf32(v.z); v.w = to_tf32(v.w);
        out[i] = v;
    }
}

// ===========================================================================
// GEMM smem (3 stages): As[128][36] Bs[32][136] per stage.
// ===========================================================================
#define G_AS(s) ((s) * 4608)
#define G_BS(s) (13824 + (s) * 4352)
#define G_SMEM_B 107520

// ---------------------------------------------------------------------------
// fused qkv GEMM + LayerNorm + split. 128 thr (4 warps), warp tile 64x64,
// CTA tile 128x128 (= 2 complete heads). Outputs q,k,v in [BH,N,D].
// ---------------------------------------------------------------------------
__global__ __launch_bounds__(128, 2) void gemm_qkv_ln(
    const float* __restrict__ A, const float* __restrict__ Bm,
    const float* __restrict__ qg, const float* __restrict__ qb,
    const float* __restrict__ kg, const float* __restrict__ kb,
    float* __restrict__ Qo, float* __restrict__ Ko, float* __restrict__ Vo)
{
    extern __shared__ float sg[];
    const uint32_t sb = smem_u32(sg);

    const int tid  = threadIdx.x;
    const int lane = tid & 31, wid = tid >> 5;
    const int g = lane >> 2, tg = lane & 3;
    const int wm = (wid & 1) * 64, wn = (wid >> 1) * 64;
    const int m0 = blockIdx.y * 128, n0 = blockIdx.x * 128;
    const int K = Cc, Nc = QKVC;

    float acc[4][8][4];
    #pragma unroll
    for (int i = 0; i < 4; i++)
        #pragma unroll
        for (int j = 0; j < 8; j++)
            #pragma unroll
            for (int r = 0; r < 4; r++) acc[i][j][r] = 0.f;

    auto issue = [&](int it, int s) {
        const int k0 = it * 32;
        #pragma unroll
        for (int i = 0; i < 8; i++) {
            int idx = tid + i * 128;
            int row = idx >> 3, kk = (idx & 7) * 4;
            cp16(sb + (G_AS(s) + row * 36 + kk) * 4,
                 A + (size_t)(m0 + row) * K + k0 + kk);
        }
        #pragma unroll
        for (int i = 0; i < 8; i++) {
            int idx = tid + i * 128;
            int kr = idx >> 5, n4 = (idx & 31) * 4;
            cp16(sb + (G_BS(s) + kr * 136 + n4) * 4,
                 Bm + (size_t)(k0 + kr) * Nc + n0 + n4);
        }
        CP_COMMIT();
    };

    const int ITERS = K / 32;          // 24
    issue(0, 0); issue(1, 1); issue(2, 2);
    CP_WAIT(2);
    __syncthreads();

    for (int it = 0; it < ITERS; ++it) {
        const float* As = sg + G_AS(it % 3);
        const float* Bs = sg + G_BS(it % 3);
        #pragma unroll
        for (int ks = 0; ks < 4; ks++) {
            const int kk = ks * 8;
            uint32_t afr[4][4], bfr[8][2];
            #pragma unroll
            for (int mt = 0; mt < 4; mt++) {
                const float* ab = As + (wm + mt * 16 + g) * 36 + kk + tg;
                afr[mt][0] = fu(ab[0]);
                afr[mt][1] = fu(ab[8 * 36]);
                afr[mt][2] = fu(ab[4]);
                afr[mt][3] = fu(ab[8 * 36 + 4]);
            }
            #pragma unroll
            for (int nt = 0; nt < 8; nt++) {
                const float* bb = Bs + (kk + tg) * 136 + wn + nt * 8 + g;
                bfr[nt][0] = fu(bb[0]);
                bfr[nt][1] = fu(bb[4 * 136]);
            }
            #pragma unroll
            for (int mt = 0; mt < 4; mt++)
                #pragma unroll
                for (int nt = 0; nt < 8; nt++)
                    mma8(acc[mt][nt], afr[mt], bfr[nt]);
        }
        __syncthreads();
        if (it + 3 < ITERS)      { issue(it + 3, (it + 3) % 3); CP_WAIT(2); }
        else if (it + 2 < ITERS) { CP_WAIT(1); }
        else if (it + 1 < ITERS) { CP_WAIT(0); }
        __syncthreads();
    }

    // ---- stage accumulators into Cs[128][132] ----
    float* Cs = sg;
    #pragma unroll
    for (int mt = 0; mt < 4; mt++) {
        int row = wm + mt * 16 + g;
        #pragma unroll
        for (int nt = 0; nt < 8; nt++) {
            int col = wn + nt * 8 + 2 * tg;
            *(float2*)(Cs + row * 132 + col) =
                make_float2(acc[mt][nt][0], acc[mt][nt][1]);
            *(float2*)(Cs + (row + 8) * 132 + col) =
                make_float2(acc[mt][nt][2], acc[mt][nt][3]);
        }
    }
    __syncthreads();

    // ---- LN / split: 8 lanes per row-head ----
    const int sect  = n0 / 768;          // 0=q, 1=k, 2=v
    const int hbase = (n0 % 768) / 64;
    const int oct = lane >> 3, li = lane & 7;
    float* outp = (sect == 0) ? Qo : (sect == 1) ? Ko : Vo;
    const float* gam = (sect == 0) ? qg : kg;
    const float* bet = (sect == 0) ? qb : kb;
    const float qs = (sect == 0) ? 0.125f : 1.0f;

    float4 ga0, ga1, be0, be1;
    if (sect < 2) {
        ga0 = *(const float4*)(gam + li * 8);
        ga1 = *(const float4*)(gam + li * 8 + 4);
        be0 = *(const float4*)(bet + li * 8);
        be1 = *(const float4*)(bet + li * 8 + 4);
    }

    for (int itr = 0; itr < 16; itr++) {
        int rh = wid * 64 + itr * 4 + oct;      // 0..255
        int row = rh >> 1, hh = rh & 1;
        const float* src = Cs + row * 132 + hh * 64 + li * 8;
        float4 f0 = *(const float4*)(src);
        float4 f1 = *(const float4*)(src + 4);
        int token = m0 + row;
        int b = token >> 11, n = token & 2047;
        float* dst = outp +
            (((size_t)(b * Hh + hbase + hh) * Nn + n) << 6) + li * 8;
        if (sect < 2) {
            float s8 = f0.x + f0.y + f0.z + f0.w + f1.x + f1.y + f1.z + f1.w;
            float q8 = f0.x*f0.x + f0.y*f0.y + f0.z*f0.z + f0.w*f0.w +
                       f1.x*f1.x + f1.y*f1.y + f1.z*f1.z + f1.w*f1.w;
            #pragma unroll
            for (int off = 1; off <= 4; off <<= 1) {
                s8 += __shfl_xor_sync(0xffffffffu, s8, off);
                q8 += __shfl_xor_sync(0xffffffffu, q8, off);
            }
            float mean = s8 * (1.f / 64.f);
            float var  = q8 * (1.f / 64.f) - mean * mean;
            float rstd = rsqrtf(var + 1e-5f);
            f0.x = to_tf32(((f0.x - mean) * rstd * ga0.x + be0.x) * qs);
            f0.y = to_tf32(((f0.y - mean) * rstd * ga0.y + be0.y) * qs);
            f0.z = to_tf32(((f0.z - mean) * rstd * ga0.z + be0.z) * qs);
            f0.w = to_tf32(((f0.w - mean) * rstd * ga0.w + be0.w) * qs);
            f1.x = to_tf32(((f1.x - mean) * rstd * ga1.x + be1.x) * qs);
            f1.y = to_tf32(((f1.y - mean) * rstd * ga1.y + be1.y) * qs);
            f1.z = to_tf32(((f1.z - mean) * rstd * ga1.z + be1.z) * qs);
            f1.w = to_tf32(((f1.w - mean) * rstd * ga1.w + be1.w) * qs);
        } else {
            f0.x = to_tf32(f0.x); f0.y = to_tf32(f0.y);
            f0.z = to_tf32(f0.z); f0.w = to_tf32(f0.w);
            f1.x = to_tf32(f1.x); f1.y = to_tf32(f1.y);
            f1.z = to_tf32(f1.z); f1.w = to_tf32(f1.w);
        }
        *(float4*)(dst)     = f0;
        *(float4*)(dst + 4) = f1;
    }
}

// ===========================================================================
// proj GEMM. 128 thr, warp tile 64x64, 3-stage. A remapped from [BH,N,D].
// ===========================================================================
__global__ __launch_bounds__(128, 2) void gemm_proj(
    const float* __restrict__ A, const float* __restrict__ Bm,
    const float* __restrict__ bias, float* __restrict__ C)
{
    extern __shared__ float sg[];
    const uint32_t sb = smem_u32(sg);

    const int tid  = threadIdx.x;
    const int lane = tid & 31, wid = tid >> 5;
    const int g = lane >> 2, tg = lane & 3;
    const int wm = (wid & 1) * 64, wn = (wid >> 1) * 64;
    const int m0 = blockIdx.y * 128, n0 = blockIdx.x * 128;
    const int K = Cc, Nc = Cc;

    float acc[4][8][4];
    #pragma unroll
    for (int i = 0; i < 4; i++)
        #pragma unroll
        for (int j = 0; j < 8; j++)
            #pragma unroll
            for (int r = 0; r < 4; r++) acc[i][j][r] = 0.f;

    auto issue = [&](int it, int s) {
        const int k0 = it * 32;
        #pragma unroll
        for (int i = 0; i < 8; i++) {
            int idx = tid + i * 128;
            int row = idx >> 3, kk = (idx & 7) * 4;
            int gk = k0 + kk;
            int h = gk >> 6, d0 = gk & 63;
            int gm = m0 + row, b = gm >> 11, n = gm & 2047;
            cp16(sb + (G_AS(s) + row * 36 + kk) * 4,
                 A + (((size_t)(b * Hh + h) * Nn + n) << 6) + d0);
        }
        #pragma unroll
        for (int i = 0; i < 8; i++) {
            int idx = tid + i * 128;
            int kr = idx >> 5, n4 = (idx & 31) * 4;
            cp16(sb + (G_BS(s) + kr * 136 + n4) * 4,
                 Bm + (size_t)(k0 + kr) * Nc + n0 + n4);
        }
        CP_COMMIT();
    };

    const int ITERS = K / 32;          // 24
    issue(0, 0); issue(1, 1); issue(2, 2);
    CP_WAIT(2);
    __syncthreads();

    for (int it = 0; it < ITERS; ++it) {
        const float* As = sg + G_AS(it % 3);
        const float* Bs = sg + G_BS(it % 3);
        #pragma unroll
        for (int ks = 0; ks < 4; ks++) {
            const int kk = ks * 8;
            uint32_t afr[4][4], bfr[8][2];
            #pragma unroll
            for (int mt = 0; mt < 4; mt++) {
                const float* ab = As + (wm + mt * 16 + g) * 36 + kk + tg;
                afr[mt][0] = fu(ab[0]);
                afr[mt][1] = fu(ab[8 * 36]);
                afr[mt][2] = fu(ab[4]);
                afr[mt][3] = fu(ab[8 * 36 + 4]);
            }
            #pragma unroll
            for (int nt = 0; nt < 8; nt++) {
                const float* bb = Bs + (kk + tg) * 136 + wn + nt * 8 + g;
                bfr[nt][0] = fu(bb[0]);
                bfr[nt][1] = fu(bb[4 * 136]);
            }
            #pragma unroll
            for (int mt = 0; mt < 4; mt++)
                #pragma unroll
                for (int nt = 0; nt < 8; nt++)
                    mma8(acc[mt][nt], afr[mt], bfr[nt]);
        }
        __syncthreads();
        if (it + 3 < ITERS)      { issue(it + 3, (it + 3) % 3); CP_WAIT(2); }
        else if (it + 2 < ITERS) { CP_WAIT(1); }
        else if (it + 1 < ITERS) { CP_WAIT(0); }
        __syncthreads();
    }

    #pragma unroll
    for (int mt = 0; mt < 4; mt++) {
        const int r0 = m0 + wm + mt * 16 + g;
        #pragma unroll
        for (int nt = 0; nt < 8; nt++) {
            const int col = n0 + wn + nt * 8 + 2 * tg;
            float bx = bias[col], by = bias[col + 1];
            float2 v0 = { acc[mt][nt][0] + bx, acc[mt][nt][1] + by };
            float2 v1 = { acc[mt][nt][2] + bx, acc[mt][nt][3] + by };
            *(float2*)(C + (size_t)r0 * Nc + col) = v0;
            *(float2*)(C + (size_t)(r0 + 8) * Nc + col) = v1;
        }
    }
}

// ===========================================================================
// Flash attention. Q-tile 256, 8 warps x 32 q-rows (mt=2), kv-tile 64,
// 2-stage cp.async. Smem: Qs[256][68] Ps[256][68] Ks{2}[64][68] Vs{2}[64][72]
// = 52736 floats = 210944 B.
// ===========================================================================
#define A_QS 0
#define A_PS 17408
#define A_KS(s) (34816 + (s) * 4352)
#define A_VS(s) (43520 + (s) * 4608)
#define ATTN_SMEM_B 210944

__global__ __launch_bounds__(256) void attn_ca(
    const float* __restrict__ Qg, const float* __restrict__ Kg,
    const float* __restrict__ Vg, float* __restrict__ Og)
{
    extern __shared__ float sg[];
    const uint32_t sb = smem_u32(sg);

    const int tid = threadIdx.x, lane = tid & 31, w = tid >> 5;
    const int g = lane >> 2, tg = lane & 3;
    const int bh = blockIdx.y, q0 = blockIdx.x * 256;

    const float* Qp = Qg + ((size_t)bh * Nn + q0) * 64;
    const float* Kp = Kg + (size_t)bh * Nn * 64;
    const float* Vp = Vg + (size_t)bh * Nn * 64;

    auto issueKV = [&](int it, int s) {
        const int k0 = it * 64;
        #pragma unroll
        for (int i = 0; i < 4; i++) {
            int idx = tid + i * 256;
            int row = idx >> 4, c4 = (idx & 15) * 4;
            cp16(sb + (A_KS(s) + row * 68 + c4) * 4,
                 Kp + (size_t)(k0 + row) * 64 + c4);
            cp16(sb + (A_VS(s) + row * 72 + c4) * 4,
                 Vp + (size_t)(k0 + row) * 64 + c4);
        }
        CP_COMMIT();
    };

    // prologue: {Q + KV0} group0, KV1 group1
    #pragma unroll
    for (int i = 0; i < 16; i++) {
        int idx = tid + i * 256;
        int row = idx >> 4, c4 = (idx & 15) * 4;
        cp16(sb + (A_QS + row * 68 + c4) * 4, Qp + (size_t)row * 64 + c4);
    }
    issueKV(0, 0);
    issueKV(1, 1);

    float mr[2][2], lr[2][2];
    #pragma unroll
    for (int mt = 0; mt < 2; mt++) {
        mr[mt][0] = -CUDART_INF_F; mr[mt][1] = -CUDART_INF_F;
        lr[mt][0] = 0.f; lr[mt][1] = 0.f;
    }
    float o[2][8][4];
    #pragma unroll
    for (int mt = 0; mt < 2; mt++)
        #pragma unroll
        for (int i = 0; i < 8; i++)
            #pragma unroll
            for (int j = 0; j < 4; j++) o[mt][i][j] = 0.f;

    const int ITERS = 32;
    for (int it = 0; it < ITERS; ++it) {
        if (it + 1 < ITERS) { issueKV(it + 1, (it + 1) & 1); CP_WAIT(1); }
        else                { CP_WAIT(0); }
        __syncthreads();

        const float* Qs = sg + A_QS;
        const float* Ks = sg + A_KS(it & 1);
        const float* Vs = sg + A_VS(it & 1);
        float* Ps = sg + A_PS;

        // ---- S = Q K^T (rows w*32 + mt*16 + {g, g+8}) ----
        float s[2][8][4];
        #pragma unroll
        for (int mt = 0; mt < 2; mt++)
            #pragma unroll
            for (int i = 0; i < 8; i++)
                #pragma unroll
                for (int j = 0; j < 4; j++) s[mt][i][j] = 0.f;

        #pragma unroll
        for (int ks = 0; ks < 8; ks++) {
            uint32_t afr[2][4], bfr[8][2];
            #pragma unroll
            for (int mt = 0; mt < 2; mt++) {
                const float* ab = Qs + (w * 32 + mt * 16 + g) * 68 + ks * 8 + tg;
                afr[mt][0] = fu(ab[0]);
                afr[mt][1] = fu(ab[8 * 68]);
                afr[mt][2] = fu(ab[4]);
                afr[mt][3] = fu(ab[8 * 68 + 4]);
            }
            #pragma unroll
            for (int nt = 0; nt < 8; nt++) {
                const float* bb = Ks + (nt * 8 + g) * 68 + ks * 8 + tg;
                bfr[nt][0] = fu(bb[0]);
                bfr[nt][1] = fu(bb[4]);
            }
            #pragma unroll
            for (int mt = 0; mt < 2; mt++)
                #pragma unroll
                for (int nt = 0; nt < 8; nt++)
                    mma8(s[mt][nt], afr[mt], bfr[nt]);
        }

        // ---- online softmax per m-tile ----
        #pragma unroll
        for (int mt = 0; mt < 2; mt++) {
            float mx0 = -CUDART_INF_F, mx1 = -CUDART_INF_F;
            #pragma unroll
            for (int nt = 0; nt < 8; nt++) {
                mx0 = fmaxf(mx0, fmaxf(s[mt][nt][0], s[mt][nt][1]));
                mx1 = fmaxf(mx1, fmaxf(s[mt][nt][2], s[mt][nt][3]));
            }
            mx0 = fmaxf(mx0, __shfl_xor_sync(0xffffffffu, mx0, 1));
            mx0 = fmaxf(mx0, __shfl_xor_sync(0xffffffffu, mx0, 2));
            mx1 = fmaxf(mx1, __shfl_xor_sync(0xffffffffu, mx1, 1));
            mx1 = fmaxf(mx1, __shfl_xor_sync(0xffffffffu, mx1, 2));

            const float mn0 = fmaxf(mr[mt][0], mx0), mn1 = fmaxf(mr[mt][1], mx1);
            const float cr0 = __expf(mr[mt][0] - mn0), cr1 = __expf(mr[mt][1] - mn1);
            float ps0 = 0.f, ps1 = 0.f;
            #pragma unroll
            for (int nt = 0; nt < 8; nt++) {
                float p00 = __expf(s[mt][nt][0] - mn0);
                float p01 = __expf(s[mt][nt][1] - mn0);
                float p10 = __expf(s[mt][nt][2] - mn1);
                float p11 = __expf(s[mt][nt][3] - mn1);
                ps0 += p00 + p01;
                ps1 += p10 + p11;
                float2 w0 = { to_tf32(p00), to_tf32(p01) };
                float2 w1 = { to_tf32(p10), to_tf32(p11) };
                *(float2*)(Ps + (w * 32 + mt * 16 + g) * 68 + nt * 8 + 2 * tg) = w0;
                *(float2*)(Ps + (w * 32 + mt * 16 + g + 8) * 68 + nt * 8 + 2 * tg) = w1;
            }
            ps0 += __shfl_xor_sync(0xffffffffu, ps0, 1);
            ps0 += __shfl_xor_sync(0xffffffffu, ps0, 2);
            ps1 += __shfl_xor_sync(0xffffffffu, ps1, 1);
            ps1 += __shfl_xor_sync(0xffffffffu, ps1, 2);
            lr[mt][0] = lr[mt][0] * cr0 + ps0;
            lr[mt][1] = lr[mt][1] * cr1 + ps1;
            mr[mt][0] = mn0; mr[mt][1] = mn1;
            #pragma unroll
            for (int nt = 0; nt < 8; nt++) {
                o[mt][nt][0] *= cr0; o[mt][nt][1] *= cr0;
                o[mt][nt][2] *= cr1; o[mt][nt][3] *= cr1;
            }
        }
        __syncwarp();   // Ps rows are warp-private

        // ---- O += P V ----
        #pragma unroll
        for (int ks = 0; ks < 8; ks++) {
            uint32_t ap[2][4], bfr[8][2];
            #pragma unroll
            for (int mt = 0; mt < 2; mt++) {
                const float* pb = Ps + (w * 32 + mt * 16 + g) * 68 + ks * 8 + tg;
                ap[mt][0] = fu(pb[0]);
                ap[mt][1] = fu(pb[8 * 68]);
                ap[mt][2] = fu(pb[4]);
                ap[mt][3] = fu(pb[8 * 68 + 4]);
            }
            #pragma unroll
            for (int nt = 0; nt < 8; nt++) {
                const float* vb = Vs + (ks * 8 + tg) * 72 + nt * 8 + g;
                bfr[nt][0] = fu(vb[0]);
                bfr[nt][1] = fu(vb[4 * 72]);
            }
            #pragma unroll
            for (int mt = 0; mt < 2; mt++)
                #pragma unroll
                for (int nt = 0; nt < 8; nt++)
                    mma8(o[mt][nt], ap[mt], bfr[nt]);
        }
        __syncthreads();   // release K/V stage
    }

    // ---- epilogue (tf32-rounded: feeds proj GEMM) ----
    #pragma unroll
    for (int mt = 0; mt < 2; mt++) {
        const float inv0 = 1.f / lr[mt][0], inv1 = 1.f / lr[mt][1];
        const int r0 = q0 + w * 32 + mt * 16 + g;
        #pragma unroll
        for (int nt = 0; nt < 8; nt++) {
            const int col = nt * 8 + 2 * tg;
            float2 v0 = { to_tf32(o[mt][nt][0] * inv0), to_tf32(o[mt][nt][1] * inv0) };
            float2 v1 = { to_tf32(o[mt][nt][2] * inv1), to_tf32(o[mt][nt][3] * inv1) };
            *(float2*)(Og + ((size_t)bh * Nn + r0) * 64 + col) = v0;
            *(float2*)(Og + ((size_t)bh * Nn + r0 + 8) * 64 + col) = v1;
        }
    }
}

// ---------------------------------------------------------------------------
extern "C" void kernel_launch(void* const* d_in, const int* in_sizes, int n_in,
                              void* d_out, int out_size)
{
    const float* x       = (const float*)d_in[0];
    const float* w_qkv   = (const float*)d_in[1];
    const float* q_gamma = (const float*)d_in[2];
    const float* q_beta  = (const float*)d_in[3];
    const float* k_gamma = (const float*)d_in[4];
    const float* k_beta  = (const float*)d_in[5];
    const float* w_proj  = (const float*)d_in[6];
    const float* b_proj  = (const float*)d_in[7];
    float* out = (float*)d_out;

    float *q, *k, *v, *o, *xr, *wq, *wp;
    cudaGetSymbolAddress((void**)&q,  g_q);
    cudaGetSymbolAddress((void**)&k,  g_k);
    cudaGetSymbolAddress((void**)&v,  g_v);
    cudaGetSymbolAddress((void**)&o,  g_o);
    cudaGetSymbolAddress((void**)&xr, g_x);
    cudaGetSymbolAddress((void**)&wq, g_wq);
    cudaGetSymbolAddress((void**)&wp, g_wp);

    cudaFuncSetAttribute(gemm_qkv_ln,
                         cudaFuncAttributeMaxDynamicSharedMemorySize, G_SMEM_B);
    cudaFuncSetAttribute(gemm_proj,
                         cudaFuncAttributeMaxDynamicSharedMemorySize, G_SMEM_B);
    cudaFuncSetAttribute(attn_ca,
                         cudaFuncAttributeMaxDynamicSharedMemorySize, ATTN_SMEM_B);

    // 0) tf32 pre-round of GEMM inputs
    {
        int n4x = Mm * Cc / 4;
        int n4q = Cc * QKVC / 4;
        int n4p = Cc * Cc / 4;
        round4_k<<<(n4x + 255) / 256, 256>>>((const float4*)x, (float4*)xr, n4x);
        round4_k<<<(n4q + 255) / 256, 256>>>((const float4*)w_qkv, (float4*)wq, n4q);
        round4_k<<<(n4p + 255) / 256, 256>>>((const float4*)w_proj, (float4*)wp, n4p);
    }

    // 1) fused qkv GEMM + LayerNorm + split
    gemm_qkv_ln<<<dim3(QKVC / 128, Mm / 128), 128, G_SMEM_B>>>(
        xr, wq, q_gamma, q_beta, k_gamma, k_beta, q, k, v);

    // 2) flash attention
    attn_ca<<<dim3(Nn / 256, BH), 256, ATTN_SMEM_B>>>(q, k, v, o);

    // 3) out = attn_out @ w_proj + b
    gemm_proj<<<dim3(Cc / 128, Mm / 128), 128, G_SMEM_B>>>(
        o, wp, b_proj, out);
}

// round 10
// speedup vs baseline: 7.5174x; 1.9186x over previous
#include <cuda_runtime.h>
#include <cuda_fp16.h>
#include <math_constants.h>
#include <cstdint>

// Problem constants
#define Bb 4
#define Nn 2048
#define Cc 768
#define Hh 12
#define Dd 64
#define Mm (Bb * Nn)        // 8192
#define QKVC (3 * Cc)       // 2304
#define BH (Bb * Hh)        // 48

// ---------------- scratch (device globals; no allocation allowed) ----------
__device__ __align__(256) __half g_q[(size_t)BH * Nn * Dd];  // [BH,N,D]
__device__ __align__(256) __half g_k[(size_t)BH * Nn * Dd];
__device__ __align__(256) __half g_v[(size_t)BH * Nn * Dd];
__device__ __align__(256) __half g_o[(size_t)BH * Nn * Dd];
__device__ __align__(256) __half g_x[(size_t)Mm * Cc];       // half x
__device__ __align__(256) __half g_wq[(size_t)Cc * QKVC];    // half w_qkv
__device__ __align__(256) __half g_wp[(size_t)Cc * Cc];      // half w_proj

// ===========================================================================
// helpers
// ===========================================================================
__device__ __forceinline__ void mma16(float* d, const uint32_t* a, const uint32_t* b) {
    asm volatile(
        "mma.sync.aligned.m16n8k16.row.col.f32.f16.f16.f32 "
        "{%0,%1,%2,%3}, {%4,%5,%6,%7}, {%8,%9}, {%0,%1,%2,%3};\n"
        : "+f"(d[0]), "+f"(d[1]), "+f"(d[2]), "+f"(d[3])
        : "r"(a[0]), "r"(a[1]), "r"(a[2]), "r"(a[3]),
          "r"(b[0]), "r"(b[1]));
}
__device__ __forceinline__ void ldsm4(uint32_t* r, uint32_t addr) {
    asm volatile("ldmatrix.sync.aligned.m8n8.x4.shared.b16 {%0,%1,%2,%3}, [%4];"
                 : "=r"(r[0]), "=r"(r[1]), "=r"(r[2]), "=r"(r[3]) : "r"(addr));
}
__device__ __forceinline__ void ldsm4t(uint32_t* r, uint32_t addr) {
    asm volatile("ldmatrix.sync.aligned.m8n8.x4.trans.shared.b16 {%0,%1,%2,%3}, [%4];"
                 : "=r"(r[0]), "=r"(r[1]), "=r"(r[2]), "=r"(r[3]) : "r"(addr));
}
__device__ __forceinline__ uint32_t h2u(__half2 h) { return *(uint32_t*)&h; }
__device__ __forceinline__ uint32_t smem_u32(const void* p) {
    uint32_t a;
    asm("{ .reg .u64 t; cvta.to.shared.u64 t, %1; cvt.u32.u64 %0, t; }"
        : "=r"(a) : "l"(p));
    return a;
}
__device__ __forceinline__ void cp16(uint32_t dst, const void* src) {
    asm volatile("cp.async.cg.shared.global [%0], [%1], 16;\n"
                 :: "r"(dst), "l"(src));
}
#define CP_COMMIT() asm volatile("cp.async.commit_group;\n" ::: "memory")
#define CP_WAIT(N)  asm volatile("cp.async.wait_group %0;\n" :: "n"(N) : "memory")

// ===========================================================================
// fp32 -> fp16 conversion pass
// ===========================================================================
__global__ void tohalf4_k(const float4* __restrict__ in, uint2* __restrict__ out,
                          int n4)
{
    int i = blockIdx.x * blockDim.x + threadIdx.x;
    if (i < n4) {
        float4 v = in[i];
        __half2 h0 = __floats2half2_rn(v.x, v.y);
        __half2 h1 = __floats2half2_rn(v.z, v.w);
        out[i] = make_uint2(h2u(h0), h2u(h1));
    }
}

// ===========================================================================
// fp16 GEMM smem (3 stages, bytes): As[128][40h]=10240 B, Bs[32][136h]=8704 B.
// ===========================================================================
#define GA(s) ((s) * 10240)
#define GB(s) (30720 + (s) * 8704)
#define G_SMEM_B 67584      // max(3-stage pipeline 56832, Cs 128*132*4)

// ---------------------------------------------------------------------------
// fused qkv GEMM + LayerNorm + split. 128 thr (4 warps), warp 64x64,
// CTA tile 128x128 (2 heads), k-chunk 32 (2 k16 steps). Outputs half q/k/v.
// ---------------------------------------------------------------------------
__global__ __launch_bounds__(128, 2) void gemm_qkv_ln(
    const __half* __restrict__ A, const __half* __restrict__ Bm,
    const float* __restrict__ qg, const float* __restrict__ qb,
    const float* __restrict__ kg, const float* __restrict__ kb,
    __half* __restrict__ Qo, __half* __restrict__ Ko, __half* __restrict__ Vo)
{
    extern __shared__ float sg[];
    const uint32_t sb = smem_u32(sg);

    const int tid  = threadIdx.x;
    const int lane = tid & 31, wid = tid >> 5;
    const int g = lane >> 2, tg = lane & 3;
    const int wm = (wid & 1) * 64, wn = (wid >> 1) * 64;
    const int m0 = blockIdx.y * 128, n0 = blockIdx.x * 128;
    const int K = Cc, Nc = QKVC;

    float acc[4][8][4];
    #pragma unroll
    for (int i = 0; i < 4; i++)
        #pragma unroll
        for (int j = 0; j < 8; j++)
            #pragma unroll
            for (int r = 0; r < 4; r++) acc[i][j][r] = 0.f;

    auto issue = [&](int it, int s) {
        const int k0 = it * 32;
        #pragma unroll
        for (int i = 0; i < 4; i++) {              // A: 128 rows x 4 chunks
            int idx = tid + i * 128;
            int row = idx >> 2, kk = (idx & 3) * 8;
            cp16(sb + GA(s) + row * 80 + kk * 2,
                 A + (size_t)(m0 + row) * K + k0 + kk);
        }
        #pragma unroll
        for (int i = 0; i < 4; i++) {              // B: 32 rows x 16 chunks
            int idx = tid + i * 128;
            int kr = idx >> 4, nc = (idx & 15) * 8;
            cp16(sb + GB(s) + kr * 272 + nc * 2,
                 Bm + (size_t)(k0 + kr) * Nc + n0 + nc);
        }
        CP_COMMIT();
    };

    // ldmatrix lane bases
    const int j8 = lane >> 3, i8 = lane & 7;
    const uint32_t aoff = (uint32_t)((wm + (j8 & 1) * 8 + i8) * 80 + (j8 >> 1) * 16);
    const int psel = lane >> 4, kh = (lane >> 3) & 1;
    const uint32_t boff = (uint32_t)((kh * 8 + i8) * 272 + (wn + psel * 8) * 2);

    const int ITERS = K / 32;          // 24
    issue(0, 0); issue(1, 1); issue(2, 2);
    CP_WAIT(2);
    __syncthreads();

    for (int it = 0; it < ITERS; ++it) {
        const uint32_t sA = sb + GA(it % 3), sB = sb + GB(it % 3);
        #pragma unroll
        for (int ks = 0; ks < 2; ks++) {
            uint32_t afr[4][4], bfr[4][4];
            #pragma unroll
            for (int mt = 0; mt < 4; mt++)
                ldsm4(afr[mt], sA + aoff + mt * 16 * 80 + ks * 32);
            #pragma unroll
            for (int np = 0; np < 4; np++)
                ldsm4t(bfr[np], sB + boff + ks * 16 * 272 + np * 32);
            #pragma unroll
            for (int mt = 0; mt < 4; mt++)
                #pragma unroll
                for (int nt = 0; nt < 8; nt++)
                    mma16(acc[mt][nt], afr[mt], &bfr[nt >> 1][(nt & 1) * 2]);
        }
        __syncthreads();
        if (it + 3 < ITERS)      { issue(it + 3, (it + 3) % 3); CP_WAIT(2); }
        else if (it + 2 < ITERS) { CP_WAIT(1); }
        else if (it + 1 < ITERS) { CP_WAIT(0); }
        __syncthreads();
    }

    // ---- stage accumulators into Cs[128][132] fp32 ----
    float* Cs = sg;
    #pragma unroll
    for (int mt = 0; mt < 4; mt++) {
        int row = wm + mt * 16 + g;
        #pragma unroll
        for (int nt = 0; nt < 8; nt++) {
            int col = wn + nt * 8 + 2 * tg;
            *(float2*)(Cs + row * 132 + col) =
                make_float2(acc[mt][nt][0], acc[mt][nt][1]);
            *(float2*)(Cs + (row + 8) * 132 + col) =
                make_float2(acc[mt][nt][2], acc[mt][nt][3]);
        }
    }
    __syncthreads();

    // ---- LN / split (outputs half) ----
    const int sect  = n0 / 768;          // 0=q, 1=k, 2=v
    const int hbase = (n0 % 768) / 64;
    const int oct = lane >> 3, li = lane & 7;
    __half* outp = (sect == 0) ? Qo : (sect == 1) ? Ko : Vo;
    const float* gam = (sect == 0) ? qg : kg;
    const float* bet = (sect == 0) ? qb : kb;
    const float qs = (sect == 0) ? 0.125f : 1.0f;

    float4 ga0, ga1, be0, be1;
    if (sect < 2) {
        ga0 = *(const float4*)(gam + li * 8);
        ga1 = *(const float4*)(gam + li * 8 + 4);
        be0 = *(const float4*)(bet + li * 8);
        be1 = *(const float4*)(bet + li * 8 + 4);
    }

    for (int itr = 0; itr < 16; itr++) {
        int rh = wid * 64 + itr * 4 + oct;
        int row = rh >> 1, hh = rh & 1;
        const float* src = Cs + row * 132 + hh * 64 + li * 8;
        float4 f0 = *(const float4*)(src);
        float4 f1 = *(const float4*)(src + 4);
        int token = m0 + row;
        int b = token >> 11, n = token & 2047;
        __half* dst = outp +
            (((size_t)(b * Hh + hbase + hh) * Nn + n) << 6) + li * 8;
        if (sect < 2) {
            float s8 = f0.x + f0.y + f0.z + f0.w + f1.x + f1.y + f1.z + f1.w;
            float q8 = f0.x*f0.x + f0.y*f0.y + f0.z*f0.z + f0.w*f0.w +
                       f1.x*f1.x + f1.y*f1.y + f1.z*f1.z + f1.w*f1.w;
            #pragma unroll
            for (int off = 1; off <= 4; off <<= 1) {
                s8 += __shfl_xor_sync(0xffffffffu, s8, off);
                q8 += __shfl_xor_sync(0xffffffffu, q8, off);
            }
            float mean = s8 * (1.f / 64.f);
            float var  = q8 * (1.f / 64.f) - mean * mean;
            float rstd = rsqrtf(var + 1e-5f);
            f0.x = ((f0.x - mean) * rstd * ga0.x + be0.x) * qs;
            f0.y = ((f0.y - mean) * rstd * ga0.y + be0.y) * qs;
            f0.z = ((f0.z - mean) * rstd * ga0.z + be0.z) * qs;
            f0.w = ((f0.w - mean) * rstd * ga0.w + be0.w) * qs;
            f1.x = ((f1.x - mean) * rstd * ga1.x + be1.x) * qs;
            f1.y = ((f1.y - mean) * rstd * ga1.y + be1.y) * qs;
            f1.z = ((f1.z - mean) * rstd * ga1.z + be1.z) * qs;
            f1.w = ((f1.w - mean) * rstd * ga1.w + be1.w) * qs;
        }
        uint4 u;
        u.x = h2u(__floats2half2_rn(f0.x, f0.y));
        u.y = h2u(__floats2half2_rn(f0.z, f0.w));
        u.z = h2u(__floats2half2_rn(f1.x, f1.y));
        u.w = h2u(__floats2half2_rn(f1.z, f1.w));
        *(uint4*)dst = u;
    }
}

// ===========================================================================
// proj GEMM fp16: out = A@B + bias (fp32 out). A remapped from half [BH,N,D].
// ===========================================================================
__global__ __launch_bounds__(128, 2) void gemm_proj(
    const __half* __restrict__ A, const __half* __restrict__ Bm,
    const float* __restrict__ bias, float* __restrict__ C)
{
    extern __shared__ float sg[];
    const uint32_t sb = smem_u32(sg);

    const int tid  = threadIdx.x;
    const int lane = tid & 31, wid = tid >> 5;
    const int g = lane >> 2, tg = lane & 3;
    const int wm = (wid & 1) * 64, wn = (wid >> 1) * 64;
    const int m0 = blockIdx.y * 128, n0 = blockIdx.x * 128;
    const int K = Cc, Nc = Cc;

    float acc[4][8][4];
    #pragma unroll
    for (int i = 0; i < 4; i++)
        #pragma unroll
        for (int j = 0; j < 8; j++)
            #pragma unroll
            for (int r = 0; r < 4; r++) acc[i][j][r] = 0.f;

    auto issue = [&](int it, int s) {
        const int k0 = it * 32;
        #pragma unroll
        for (int i = 0; i < 4; i++) {
            int idx = tid + i * 128;
            int row = idx >> 2, kk = (idx & 3) * 8;
            int gk = k0 + kk;
            int h = gk >> 6, d0 = gk & 63;
            int gm = m0 + row, b = gm >> 11, n = gm & 2047;
            cp16(sb + GA(s) + row * 80 + kk * 2,
                 A + (((size_t)(b * Hh + h) * Nn + n) << 6) + d0);
        }
        #pragma unroll
        for (int i = 0; i < 4; i++) {
            int idx = tid + i * 128;
            int kr = idx >> 4, nc = (idx & 15) * 8;
            cp16(sb + GB(s) + kr * 272 + nc * 2,
                 Bm + (size_t)(k0 + kr) * Nc + n0 + nc);
        }
        CP_COMMIT();
    };

    const int j8 = lane >> 3, i8 = lane & 7;
    const uint32_t aoff = (uint32_t)((wm + (j8 & 1) * 8 + i8) * 80 + (j8 >> 1) * 16);
    const int psel = lane >> 4, kh = (lane >> 3) & 1;
    const uint32_t boff = (uint32_t)((kh * 8 + i8) * 272 + (wn + psel * 8) * 2);

    const int ITERS = K / 32;
    issue(0, 0); issue(1, 1); issue(2, 2);
    CP_WAIT(2);
    __syncthreads();

    for (int it = 0; it < ITERS; ++it) {
        const uint32_t sA = sb + GA(it % 3), sB = sb + GB(it % 3);
        #pragma unroll
        for (int ks = 0; ks < 2; ks++) {
            uint32_t afr[4][4], bfr[4][4];
            #pragma unroll
            for (int mt = 0; mt < 4; mt++)
                ldsm4(afr[mt], sA + aoff + mt * 16 * 80 + ks * 32);
            #pragma unroll
            for (int np = 0; np < 4; np++)
                ldsm4t(bfr[np], sB + boff + ks * 16 * 272 + np * 32);
            #pragma unroll
            for (int mt = 0; mt < 4; mt++)
                #pragma unroll
                for (int nt = 0; nt < 8; nt++)
                    mma16(acc[mt][nt], afr[mt], &bfr[nt >> 1][(nt & 1) * 2]);
        }
        __syncthreads();
        if (it + 3 < ITERS)      { issue(it + 3, (it + 3) % 3); CP_WAIT(2); }
        else if (it + 2 < ITERS) { CP_WAIT(1); }
        else if (it + 1 < ITERS) { CP_WAIT(0); }
        __syncthreads();
    }

    #pragma unroll
    for (int mt = 0; mt < 4; mt++) {
        const int r0 = m0 + wm + mt * 16 + g;
        #pragma unroll
        for (int nt = 0; nt < 8; nt++) {
            const int col = n0 + wn + nt * 8 + 2 * tg;
            float bx = bias[col], by = bias[col + 1];
            float2 v0 = { acc[mt][nt][0] + bx, acc[mt][nt][1] + by };
            float2 v1 = { acc[mt][nt][2] + bx, acc[mt][nt][3] + by };
            *(float2*)(C + (size_t)r0 * Nc + col) = v0;
            *(float2*)(C + (size_t)(r0 + 8) * Nc + col) = v1;
        }
    }
}

// ===========================================================================
// Flash attention fp16. Q-tile 256, 8 warps x 32 rows (mt=2), kv-tile 64,
// 2-stage cp.async. P stays in registers (FA2 accumulator->A-frag identity).
// Smem bytes: Qs[256][72h]=36864, Ks{2}[64][72h]=18432, Vs{2}=18432 -> 73728.
// ===========================================================================
#define A_QS 0
#define A_KS(s) (36864 + (s) * 9216)
#define A_VS(s) (55296 + (s) * 9216)
#define ATTN_SMEM_B 73728

__global__ __launch_bounds__(256) void attn_fp16(
    const __half* __restrict__ Qg, const __half* __restrict__ Kg,
    const __half* __restrict__ Vg, __half* __restrict__ Og)
{
    extern __shared__ float sg[];
    const uint32_t sb = smem_u32(sg);

    const int tid = threadIdx.x, lane = tid & 31, w = tid >> 5;
    const int g = lane >> 2, tg = lane & 3;
    const int bh = blockIdx.y, q0 = blockIdx.x * 256;

    const __half* Qp = Qg + ((size_t)bh * Nn + q0) * 64;
    const __half* Kp = Kg + (size_t)bh * Nn * 64;
    const __half* Vp = Vg + (size_t)bh * Nn * 64;

    auto issueKV = [&](int it, int s) {
        const int k0 = it * 64;
        #pragma unroll
        for (int i = 0; i < 2; i++) {
            int idx = tid + i * 256;
            int row = idx >> 3, c = (idx & 7) * 8;
            cp16(sb + A_KS(s) + row * 144 + c * 2,
                 Kp + (size_t)(k0 + row) * 64 + c);
            cp16(sb + A_VS(s) + row * 144 + c * 2,
                 Vp + (size_t)(k0 + row) * 64 + c);
        }
        CP_COMMIT();
    };

    // prologue: Q + KV0 (group0), KV1 (group1)
    #pragma unroll
    for (int i = 0; i < 8; i++) {
        int idx = tid + i * 256;
        int row = idx >> 3, c = (idx & 7) * 8;
        cp16(sb + A_QS + row * 144 + c * 2, Qp + (size_t)row * 64 + c);
    }
    issueKV(0, 0);
    issueKV(1, 1);
    CP_WAIT(1);
    __syncthreads();

    // ldmatrix lane bases
    const int j8 = lane >> 3, i8 = lane & 7;
    const uint32_t qoff = (uint32_t)((w * 32 + (j8 & 1) * 8 + i8) * 144 + (j8 >> 1) * 16);
    const int ntsel = lane >> 4, dh = (lane >> 3) & 1;        // K (non-trans)
    const uint32_t koff = (uint32_t)((ntsel * 8 + i8) * 144 + dh * 16);
    const int dsel = lane >> 4, kvh = (lane >> 3) & 1;        // V (trans)
    const uint32_t voff = (uint32_t)((kvh * 8 + i8) * 144 + dsel * 16);

    // hoist Q fragments (loop-invariant): qf[mt][ks16][4]
    uint32_t qf[2][4][4];
    #pragma unroll
    for (int mt = 0; mt < 2; mt++)
        #pragma unroll
        for (int ks = 0; ks < 4; ks++)
            ldsm4(qf[mt][ks], sb + A_QS + qoff + mt * 16 * 144 + ks * 32);

    float mr[2][2], lr[2][2];
    #pragma unroll
    for (int mt = 0; mt < 2; mt++) {
        mr[mt][0] = -CUDART_INF_F; mr[mt][1] = -CUDART_INF_F;
        lr[mt][0] = 0.f; lr[mt][1] = 0.f;
    }
    float o[2][8][4];
    #pragma unroll
    for (int mt = 0; mt < 2; mt++)
        #pragma unroll
        for (int i = 0; i < 8; i++)
            #pragma unroll
            for (int j = 0; j < 4; j++) o[mt][i][j] = 0.f;

    const int ITERS = 32;
    for (int it = 0; it < ITERS; ++it) {
        const uint32_t sK = sb + A_KS(it & 1), sV = sb + A_VS(it & 1);

        // ---- S = Q K^T ----
        float s[2][8][4];
        #pragma unroll
        for (int mt = 0; mt < 2; mt++)
            #pragma unroll
            for (int i = 0; i < 8; i++)
                #pragma unroll
                for (int j = 0; j < 4; j++) s[mt][i][j] = 0.f;

        #pragma unroll
        for (int ks = 0; ks < 4; ks++) {
            uint32_t kbf[4][4];
            #pragma unroll
            for (int np = 0; np < 4; np++)
                ldsm4(kbf[np], sK + koff + np * 16 * 144 + ks * 32);
            #pragma unroll
            for (int mt = 0; mt < 2; mt++)
                #pragma unroll
                for (int nt = 0; nt < 8; nt++)
                    mma16(s[mt][nt], qf[mt][ks], &kbf[nt >> 1][(nt & 1) * 2]);
        }

        // ---- online softmax; P packed straight into A-fragments ----
        uint32_t pf[2][4][4];
        #pragma unroll
        for (int mt = 0; mt < 2; mt++) {
            float mx0 = -CUDART_INF_F, mx1 = -CUDART_INF_F;
            #pragma unroll
            for (int nt = 0; nt < 8; nt++) {
                mx0 = fmaxf(mx0, fmaxf(s[mt][nt][0], s[mt][nt][1]));
                mx1 = fmaxf(mx1, fmaxf(s[mt][nt][2], s[mt][nt][3]));
            }
            mx0 = fmaxf(mx0, __shfl_xor_sync(0xffffffffu, mx0, 1));
            mx0 = fmaxf(mx0, __shfl_xor_sync(0xffffffffu, mx0, 2));
            mx1 = fmaxf(mx1, __shfl_xor_sync(0xffffffffu, mx1, 1));
            mx1 = fmaxf(mx1, __shfl_xor_sync(0xffffffffu, mx1, 2));

            const float mn0 = fmaxf(mr[mt][0], mx0), mn1 = fmaxf(mr[mt][1], mx1);
            const float cr0 = __expf(mr[mt][0] - mn0), cr1 = __expf(mr[mt][1] - mn1);
            float ps0 = 0.f, ps1 = 0.f;
            #pragma unroll
            for (int nt = 0; nt < 8; nt++) {
                float p00 = __expf(s[mt][nt][0] - mn0);
                float p01 = __expf(s[mt][nt][1] - mn0);
                float p10 = __expf(s[mt][nt][2] - mn1);
                float p11 = __expf(s[mt][nt][3] - mn1);
                ps0 += p00 + p01;
                ps1 += p10 + p11;
                uint32_t lo = h2u(__floats2half2_rn(p00, p01));
                uint32_t hi = h2u(__floats2half2_rn(p10, p11));
                int kb = nt >> 1;
                if ((nt & 1) == 0) { pf[mt][kb][0] = lo; pf[mt][kb][1] = hi; }
                else               { pf[mt][kb][2] = lo; pf[mt][kb][3] = hi; }
            }
            ps0 += __shfl_xor_sync(0xffffffffu, ps0, 1);
            ps0 += __shfl_xor_sync(0xffffffffu, ps0, 2);
            ps1 += __shfl_xor_sync(0xffffffffu, ps1, 1);
            ps1 += __shfl_xor_sync(0xffffffffu, ps1, 2);
            lr[mt][0] = lr[mt][0] * cr0 + ps0;
            lr[mt][1] = lr[mt][1] * cr1 + ps1;
            mr[mt][0] = mn0; mr[mt][1] = mn1;
            #pragma unroll
            for (int nt = 0; nt < 8; nt++) {
                o[mt][nt][0] *= cr0; o[mt][nt][1] *= cr0;
                o[mt][nt][2] *= cr1; o[mt][nt][3] *= cr1;
            }
        }

        // ---- O += P V ----
        #pragma unroll
        for (int ks = 0; ks < 4; ks++) {
            uint32_t vbf[4][4];
            #pragma unroll
            for (int np = 0; np < 4; np++)
                ldsm4t(vbf[np], sV + voff + ks * 16 * 144 + np * 32);
            #pragma unroll
            for (int mt = 0; mt < 2; mt++)
                #pragma unroll
                for (int nt = 0; nt < 8; nt++)
                    mma16(o[mt][nt], pf[mt][ks], &vbf[nt >> 1][(nt & 1) * 2]);
        }

        __syncthreads();                           // done reading stage it&1
        if (it + 2 < ITERS)      { issueKV(it + 2, it & 1); CP_WAIT(1); }
        else if (it + 1 < ITERS) { CP_WAIT(0); }
        __syncthreads();                           // stage (it+1)&1 visible
    }

    // ---- epilogue -> half O ----
    #pragma unroll
    for (int mt = 0; mt < 2; mt++) {
        const float inv0 = 1.f / lr[mt][0], inv1 = 1.f / lr[mt][1];
        const int r0 = q0 + w * 32 + mt * 16 + g;
        #pragma unroll
        for (int nt = 0; nt < 8; nt++) {
            const int col = nt * 8 + 2 * tg;
            __half2 h0 = __floats2half2_rn(o[mt][nt][0] * inv0, o[mt][nt][1] * inv0);
            __half2 h1 = __floats2half2_rn(o[mt][nt][2] * inv1, o[mt][nt][3] * inv1);
            *(__half2*)(Og + ((size_t)bh * Nn + r0) * 64 + col) = h0;
            *(__half2*)(Og + ((size_t)bh * Nn + r0 + 8) * 64 + col) = h1;
        }
    }
}

// ---------------------------------------------------------------------------
extern "C" void kernel_launch(void* const* d_in, const int* in_sizes, int n_in,
                              void* d_out, int out_size)
{
    const float* x       = (const float*)d_in[0];
    const float* w_qkv   = (const float*)d_in[1];
    const float* q_gamma = (const float*)d_in[2];
    const float* q_beta  = (const float*)d_in[3];
    const float* k_gamma = (const float*)d_in[4];
    const float* k_beta  = (const float*)d_in[5];
    const float* w_proj  = (const float*)d_in[6];
    const float* b_proj  = (const float*)d_in[7];
    float* out = (float*)d_out;

    __half *q, *k, *v, *o, *xh, *wq, *wp;
    cudaGetSymbolAddress((void**)&q,  g_q);
    cudaGetSymbolAddress((void**)&k,  g_k);
    cudaGetSymbolAddress((void**)&v,  g_v);
    cudaGetSymbolAddress((void**)&o,  g_o);
    cudaGetSymbolAddress((void**)&xh, g_x);
    cudaGetSymbolAddress((void**)&wq, g_wq);
    cudaGetSymbolAddress((void**)&wp, g_wp);

    cudaFuncSetAttribute(gemm_qkv_ln,
                         cudaFuncAttributeMaxDynamicSharedMemorySize, G_SMEM_B);
    cudaFuncSetAttribute(gemm_proj,
                         cudaFuncAttributeMaxDynamicSharedMemorySize, G_SMEM_B);
    cudaFuncSetAttribute(attn_fp16,
                         cudaFuncAttributeMaxDynamicSharedMemorySize, ATTN_SMEM_B);

    // 0) fp16 conversion of GEMM inputs
    {
        int n4x = Mm * Cc / 4;
        int n4q = Cc * QKVC / 4;
        int n4p = Cc * Cc / 4;
        tohalf4_k<<<(n4x + 255) / 256, 256>>>((const float4*)x, (uint2*)xh, n4x);
        tohalf4_k<<<(n4q + 255) / 256, 256>>>((const float4*)w_qkv, (uint2*)wq, n4q);
        tohalf4_k<<<(n4p + 255) / 256, 256>>>((const float4*)w_proj, (uint2*)wp, n4p);
    }

    // 1) fused qkv GEMM + LayerNorm + split (fp16 in, fp32 LN, fp16 out)
    gemm_qkv_ln<<<dim3(QKVC / 128, Mm / 128), 128, G_SMEM_B>>>(
        xh, wq, q_gamma, q_beta, k_gamma, k_beta, q, k, v);

    // 2) flash attention (fp16 operands, fp32 accum, P in registers)
    attn_fp16<<<dim3(Nn / 256, BH), 256, ATTN_SMEM_B>>>(q, k, v, o);

    // 3) out = attn_out @ w_proj + b (fp32 out)
    gemm_proj<<<dim3(Cc / 128, Mm / 128), 128, G_SMEM_B>>>(
        o, wp, b_proj, out);
}

// round 11
// speedup vs baseline: 7.7440x; 1.0301x over previous
#include <cuda_runtime.h>
#include <cuda_fp16.h>
#include <math_constants.h>
#include <cstdint>

// Problem constants
#define Bb 4
#define Nn 2048
#define Cc 768
#define Hh 12
#define Dd 64
#define Mm (Bb * Nn)        // 8192
#define QKVC (3 * Cc)       // 2304
#define BH (Bb * Hh)        // 48

// ---------------- scratch (device globals; no allocation allowed) ----------
__device__ __align__(256) __half g_q[(size_t)BH * Nn * Dd];  // [BH,N,D]
__device__ __align__(256) __half g_k[(size_t)BH * Nn * Dd];
__device__ __align__(256) __half g_v[(size_t)BH * Nn * Dd];
__device__ __align__(256) __half g_o[(size_t)BH * Nn * Dd];
__device__ __align__(256) __half g_x[(size_t)Mm * Cc];       // half x
__device__ __align__(256) __half g_wq[(size_t)Cc * QKVC];    // half w_qkv
__device__ __align__(256) __half g_wp[(size_t)Cc * Cc];      // half w_proj

// ===========================================================================
// helpers
// ===========================================================================
__device__ __forceinline__ void mma16(float* d, const uint32_t* a, const uint32_t* b) {
    asm volatile(
        "mma.sync.aligned.m16n8k16.row.col.f32.f16.f16.f32 "
        "{%0,%1,%2,%3}, {%4,%5,%6,%7}, {%8,%9}, {%0,%1,%2,%3};\n"
        : "+f"(d[0]), "+f"(d[1]), "+f"(d[2]), "+f"(d[3])
        : "r"(a[0]), "r"(a[1]), "r"(a[2]), "r"(a[3]),
          "r"(b[0]), "r"(b[1]));
}
__device__ __forceinline__ void ldsm4(uint32_t* r, uint32_t addr) {
    asm volatile("ldmatrix.sync.aligned.m8n8.x4.shared.b16 {%0,%1,%2,%3}, [%4];"
                 : "=r"(r[0]), "=r"(r[1]), "=r"(r[2]), "=r"(r[3]) : "r"(addr));
}
__device__ __forceinline__ void ldsm4t(uint32_t* r, uint32_t addr) {
    asm volatile("ldmatrix.sync.aligned.m8n8.x4.trans.shared.b16 {%0,%1,%2,%3}, [%4];"
                 : "=r"(r[0]), "=r"(r[1]), "=r"(r[2]), "=r"(r[3]) : "r"(addr));
}
__device__ __forceinline__ uint32_t h2u(__half2 h) { return *(uint32_t*)&h; }
__device__ __forceinline__ uint32_t smem_u32(const void* p) {
    uint32_t a;
    asm("{ .reg .u64 t; cvta.to.shared.u64 t, %1; cvt.u32.u64 %0, t; }"
        : "=r"(a) : "l"(p));
    return a;
}
__device__ __forceinline__ void cp16(uint32_t dst, const void* src) {
    asm volatile("cp.async.cg.shared.global [%0], [%1], 16;\n"
                 :: "r"(dst), "l"(src));
}
#define CP_COMMIT() asm volatile("cp.async.commit_group;\n" ::: "memory")
#define CP_WAIT(N)  asm volatile("cp.async.wait_group %0;\n" :: "n"(N) : "memory")

// ===========================================================================
// fp32 -> fp16 conversion pass
// ===========================================================================
__global__ void tohalf4_k(const float4* __restrict__ in, uint2* __restrict__ out,
                          int n4)
{
    int i = blockIdx.x * blockDim.x + threadIdx.x;
    if (i < n4) {
        float4 v = in[i];
        __half2 h0 = __floats2half2_rn(v.x, v.y);
        __half2 h1 = __floats2half2_rn(v.z, v.w);
        out[i] = make_uint2(h2u(h0), h2u(h1));
    }
}

// ===========================================================================
// fp16 GEMM smem (3 stages, k-chunk 64, bytes):
//   As[128][72h]=18432 B, Bs[64][136h]=17408 B per stage; 3 stages = 107520 B.
// ===========================================================================
#define GA(s) ((s) * 18432)
#define GB(s) (55296 + (s) * 17408)
#define G_SMEM_B 107520     // >= Cs reuse (128*132*4 = 67584)

// ---------------------------------------------------------------------------
// fused qkv GEMM + LayerNorm + split. 128 thr (4 warps), warp 64x64,
// CTA tile 128x128 (2 heads), k-chunk 64, single barrier per iter.
// q output folds 0.125 * log2(e) (attention works in exp2 domain).
// ---------------------------------------------------------------------------
__global__ __launch_bounds__(128, 2) void gemm_qkv_ln(
    const __half* __restrict__ A, const __half* __restrict__ Bm,
    const float* __restrict__ qg, const float* __restrict__ qb,
    const float* __restrict__ kg, const float* __restrict__ kb,
    __half* __restrict__ Qo, __half* __restrict__ Ko, __half* __restrict__ Vo)
{
    extern __shared__ float sg[];
    const uint32_t sb = smem_u32(sg);

    const int tid  = threadIdx.x;
    const int lane = tid & 31, wid = tid >> 5;
    const int g = lane >> 2, tg = lane & 3;
    const int wm = (wid & 1) * 64, wn = (wid >> 1) * 64;
    const int m0 = blockIdx.y * 128, n0 = blockIdx.x * 128;
    const int K = Cc, Nc = QKVC;

    float acc[4][8][4];
    #pragma unroll
    for (int i = 0; i < 4; i++)
        #pragma unroll
        for (int j = 0; j < 8; j++)
            #pragma unroll
            for (int r = 0; r < 4; r++) acc[i][j][r] = 0.f;

    auto issue = [&](int it, int s) {
        const int k0 = it * 64;
        #pragma unroll
        for (int i = 0; i < 8; i++) {              // A: 128 rows x 64h
            int idx = tid + i * 128;
            int row = idx >> 3, kk = (idx & 7) * 8;
            cp16(sb + GA(s) + row * 144 + kk * 2,
                 A + (size_t)(m0 + row) * K + k0 + kk);
        }
        #pragma unroll
        for (int i = 0; i < 8; i++) {              // B: 64 rows x 128h
            int idx = tid + i * 128;
            int kr = idx >> 4, nc = (idx & 15) * 8;
            cp16(sb + GB(s) + kr * 272 + nc * 2,
                 Bm + (size_t)(k0 + kr) * Nc + n0 + nc);
        }
        CP_COMMIT();
    };

    // ldmatrix lane bases
    const int j8 = lane >> 3, i8 = lane & 7;
    const uint32_t aoff = (uint32_t)((wm + (j8 & 1) * 8 + i8) * 144 + (j8 >> 1) * 16);
    const int psel = lane >> 4, kh = (lane >> 3) & 1;
    const uint32_t boff = (uint32_t)((kh * 8 + i8) * 272 + (wn + psel * 8) * 2);

    const int ITERS = K / 64;          // 12
    issue(0, 0); issue(1, 1);

    for (int it = 0; it < ITERS; ++it) {
        if (it + 1 < ITERS) CP_WAIT(1); else CP_WAIT(0);
        __syncthreads();               // stage it visible; stage (it+2)%3 free
        if (it + 2 < ITERS) issue(it + 2, (it + 2) % 3);

        const uint32_t sA = sb + GA(it % 3), sB = sb + GB(it % 3);
        #pragma unroll
        for (int ks = 0; ks < 4; ks++) {
            uint32_t afr[4][4], bfr[4][4];
            #pragma unroll
            for (int mt = 0; mt < 4; mt++)
                ldsm4(afr[mt], sA + aoff + mt * 16 * 144 + ks * 32);
            #pragma unroll
            for (int np = 0; np < 4; np++)
                ldsm4t(bfr[np], sB + boff + ks * 16 * 272 + np * 32);
            #pragma unroll
            for (int mt = 0; mt < 4; mt++)
                #pragma unroll
                for (int nt = 0; nt < 8; nt++)
                    mma16(acc[mt][nt], afr[mt], &bfr[nt >> 1][(nt & 1) * 2]);
        }
    }
    __syncthreads();                   // before Cs reuse of pipeline smem

    // ---- stage accumulators into Cs[128][132] fp32 ----
    float* Cs = sg;
    #pragma unroll
    for (int mt = 0; mt < 4; mt++) {
        int row = wm + mt * 16 + g;
        #pragma unroll
        for (int nt = 0; nt < 8; nt++) {
            int col = wn + nt * 8 + 2 * tg;
            *(float2*)(Cs + row * 132 + col) =
                make_float2(acc[mt][nt][0], acc[mt][nt][1]);
            *(float2*)(Cs + (row + 8) * 132 + col) =
                make_float2(acc[mt][nt][2], acc[mt][nt][3]);
        }
    }
    __syncthreads();

    // ---- LN / split (outputs half) ----
    const int sect  = n0 / 768;          // 0=q, 1=k, 2=v
    const int hbase = (n0 % 768) / 64;
    const int oct = lane >> 3, li = lane & 7;
    __half* outp = (sect == 0) ? Qo : (sect == 1) ? Ko : Vo;
    const float* gam = (sect == 0) ? qg : kg;
    const float* bet = (sect == 0) ? qb : kb;
    const float qs = (sect == 0) ? 0.125f * 1.44269504f : 1.0f;  // fold log2e

    float4 ga0, ga1, be0, be1;
    if (sect < 2) {
        ga0 = *(const float4*)(gam + li * 8);
        ga1 = *(const float4*)(gam + li * 8 + 4);
        be0 = *(const float4*)(bet + li * 8);
        be1 = *(const float4*)(bet + li * 8 + 4);
    }

    for (int itr = 0; itr < 16; itr++) {
        int rh = wid * 64 + itr * 4 + oct;
        int row = rh >> 1, hh = rh & 1;
        const float* src = Cs + row * 132 + hh * 64 + li * 8;
        float4 f0 = *(const float4*)(src);
        float4 f1 = *(const float4*)(src + 4);
        int token = m0 + row;
        int b = token >> 11, n = token & 2047;
        __half* dst = outp +
            (((size_t)(b * Hh + hbase + hh) * Nn + n) << 6) + li * 8;
        if (sect < 2) {
            float s8 = f0.x + f0.y + f0.z + f0.w + f1.x + f1.y + f1.z + f1.w;
            float q8 = f0.x*f0.x + f0.y*f0.y + f0.z*f0.z + f0.w*f0.w +
                       f1.x*f1.x + f1.y*f1.y + f1.z*f1.z + f1.w*f1.w;
            #pragma unroll
            for (int off = 1; off <= 4; off <<= 1) {
                s8 += __shfl_xor_sync(0xffffffffu, s8, off);
                q8 += __shfl_xor_sync(0xffffffffu, q8, off);
            }
            float mean = s8 * (1.f / 64.f);
            float var  = q8 * (1.f / 64.f) - mean * mean;
            float rstd = rsqrtf(var + 1e-5f);
            f0.x = ((f0.x - mean) * rstd * ga0.x + be0.x) * qs;
            f0.y = ((f0.y - mean) * rstd * ga0.y + be0.y) * qs;
            f0.z = ((f0.z - mean) * rstd * ga0.z + be0.z) * qs;
            f0.w = ((f0.w - mean) * rstd * ga0.w + be0.w) * qs;
            f1.x = ((f1.x - mean) * rstd * ga1.x + be1.x) * qs;
            f1.y = ((f1.y - mean) * rstd * ga1.y + be1.y) * qs;
            f1.z = ((f1.z - mean) * rstd * ga1.z + be1.z) * qs;
            f1.w = ((f1.w - mean) * rstd * ga1.w + be1.w) * qs;
        }
        uint4 u;
        u.x = h2u(__floats2half2_rn(f0.x, f0.y));
        u.y = h2u(__floats2half2_rn(f0.z, f0.w));
        u.z = h2u(__floats2half2_rn(f1.x, f1.y));
        u.w = h2u(__floats2half2_rn(f1.z, f1.w));
        *(uint4*)dst = u;
    }
}

// ===========================================================================
// proj GEMM fp16: out = A@B + bias (fp32 out). A remapped from half [BH,N,D].
// k-chunk 64, 3-stage, single barrier per iter.
// ===========================================================================
__global__ __launch_bounds__(128, 2) void gemm_proj(
    const __half* __restrict__ A, const __half* __restrict__ Bm,
    const float* __restrict__ bias, float* __restrict__ C)
{
    extern __shared__ float sg[];
    const uint32_t sb = smem_u32(sg);

    const int tid  = threadIdx.x;
    const int lane = tid & 31, wid = tid >> 5;
    const int g = lane >> 2, tg = lane & 3;
    const int wm = (wid & 1) * 64, wn = (wid >> 1) * 64;
    const int m0 = blockIdx.y * 128, n0 = blockIdx.x * 128;
    const int K = Cc, Nc = Cc;

    float acc[4][8][4];
    #pragma unroll
    for (int i = 0; i < 4; i++)
        #pragma unroll
        for (int j = 0; j < 8; j++)
            #pragma unroll
            for (int r = 0; r < 4; r++) acc[i][j][r] = 0.f;

    auto issue = [&](int it, int s) {
        const int k0 = it * 64;
        #pragma unroll
        for (int i = 0; i < 8; i++) {
            int idx = tid + i * 128;
            int row = idx >> 3, kk = (idx & 7) * 8;
            int h = (k0 + kk) >> 6;               // k0 % 64 == 0, kk < 64
            int gm = m0 + row, b = gm >> 11, n = gm & 2047;
            cp16(sb + GA(s) + row * 144 + kk * 2,
                 A + (((size_t)(b * Hh + h) * Nn + n) << 6) + ((k0 + kk) & 63));
        }
        #pragma unroll
        for (int i = 0; i < 8; i++) {
            int idx = tid + i * 128;
            int kr = idx >> 4, nc = (idx & 15) * 8;
            cp16(sb + GB(s) + kr * 272 + nc * 2,
                 Bm + (size_t)(k0 + kr) * Nc + n0 + nc);
        }
        CP_COMMIT();
    };

    const int j8 = lane >> 3, i8 = lane & 7;
    const uint32_t aoff = (uint32_t)((wm + (j8 & 1) * 8 + i8) * 144 + (j8 >> 1) * 16);
    const int psel = lane >> 4, kh = (lane >> 3) & 1;
    const uint32_t boff = (uint32_t)((kh * 8 + i8) * 272 + (wn + psel * 8) * 2);

    const int ITERS = K / 64;          // 12
    issue(0, 0); issue(1, 1);

    for (int it = 0; it < ITERS; ++it) {
        if (it + 1 < ITERS) CP_WAIT(1); else CP_WAIT(0);
        __syncthreads();
        if (it + 2 < ITERS) issue(it + 2, (it + 2) % 3);

        const uint32_t sA = sb + GA(it % 3), sB = sb + GB(it % 3);
        #pragma unroll
        for (int ks = 0; ks < 4; ks++) {
            uint32_t afr[4][4], bfr[4][4];
            #pragma unroll
            for (int mt = 0; mt < 4; mt++)
                ldsm4(afr[mt], sA + aoff + mt * 16 * 144 + ks * 32);
            #pragma unroll
            for (int np = 0; np < 4; np++)
                ldsm4t(bfr[np], sB + boff + ks * 16 * 272 + np * 32);
            #pragma unroll
            for (int mt = 0; mt < 4; mt++)
                #pragma unroll
                for (int nt = 0; nt < 8; nt++)
                    mma16(acc[mt][nt], afr[mt], &bfr[nt >> 1][(nt & 1) * 2]);
        }
    }

    #pragma unroll
    for (int mt = 0; mt < 4; mt++) {
        const int r0 = m0 + wm + mt * 16 + g;
        #pragma unroll
        for (int nt = 0; nt < 8; nt++) {
            const int col = n0 + wn + nt * 8 + 2 * tg;
            float bx = bias[col], by = bias[col + 1];
            float2 v0 = { acc[mt][nt][0] + bx, acc[mt][nt][1] + by };
            float2 v1 = { acc[mt][nt][2] + bx, acc[mt][nt][3] + by };
            *(float2*)(C + (size_t)r0 * Nc + col) = v0;
            *(float2*)(C + (size_t)(r0 + 8) * Nc + col) = v1;
        }
    }
}

// ===========================================================================
// Flash attention fp16. Q-tile 128, 128 thr (4 warps x 32 rows), kv-tile 64,
// 3-stage cp.async, single barrier per iter, exp2 domain, P in registers.
// Smem: Qs[128][72h]=18432, Ks{3}=27648, Vs{3}=27648 -> 73728 B (2 CTAs/SM).
// ===========================================================================
#define A_QS 0
#define A_KS(s) (18432 + (s) * 9216)
#define A_VS(s) (46080 + (s) * 9216)
#define ATTN_SMEM_B 73728

__global__ __launch_bounds__(128, 2) void attn_fp16(
    const __half* __restrict__ Qg, const __half* __restrict__ Kg,
    const __half* __restrict__ Vg, __half* __restrict__ Og)
{
    extern __shared__ float sg[];
    const uint32_t sb = smem_u32(sg);

    const int tid = threadIdx.x, lane = tid & 31, w = tid >> 5;
    const int g = lane >> 2, tg = lane & 3;
    const int bh = blockIdx.y, q0 = blockIdx.x * 128;

    const __half* Qp = Qg + ((size_t)bh * Nn + q0) * 64;
    const __half* Kp = Kg + (size_t)bh * Nn * 64;
    const __half* Vp = Vg + (size_t)bh * Nn * 64;

    auto issueKV = [&](int it, int s) {
        const int k0 = it * 64;
        #pragma unroll
        for (int i = 0; i < 4; i++) {
            int idx = tid + i * 128;
            int row = idx >> 3, c = (idx & 7) * 8;
            cp16(sb + A_KS(s) + row * 144 + c * 2,
                 Kp + (size_t)(k0 + row) * 64 + c);
            cp16(sb + A_VS(s) + row * 144 + c * 2,
                 Vp + (size_t)(k0 + row) * 64 + c);
        }
        CP_COMMIT();
    };

    // prologue: Q + KV0 (group0), KV1 (group1)
    #pragma unroll
    for (int i = 0; i < 8; i++) {
        int idx = tid + i * 128;
        int row = idx >> 3, c = (idx & 7) * 8;
        cp16(sb + A_QS + row * 144 + c * 2, Qp + (size_t)row * 64 + c);
    }
    issueKV(0, 0);
    issueKV(1, 1);

    // ldmatrix lane bases
    const int j8 = lane >> 3, i8 = lane & 7;
    const uint32_t qoff = (uint32_t)((w * 32 + (j8 & 1) * 8 + i8) * 144 + (j8 >> 1) * 16);
    const int ntsel = lane >> 4, dh = (lane >> 3) & 1;        // K (non-trans)
    const uint32_t koff = (uint32_t)((ntsel * 8 + i8) * 144 + dh * 16);
    const int dsel = lane >> 4, kvh = (lane >> 3) & 1;        // V (trans)
    const uint32_t voff = (uint32_t)((kvh * 8 + i8) * 144 + dsel * 16);

    float mr[2][2], lr[2][2];
    #pragma unroll
    for (int mt = 0; mt < 2; mt++) {
        mr[mt][0] = -CUDART_INF_F; mr[mt][1] = -CUDART_INF_F;
        lr[mt][0] = 0.f; lr[mt][1] = 0.f;
    }
    float o[2][8][4];
    #pragma unroll
    for (int mt = 0; mt < 2; mt++)
        #pragma unroll
        for (int i = 0; i < 8; i++)
            #pragma unroll
            for (int j = 0; j < 4; j++) o[mt][i][j] = 0.f;

    uint32_t qf[2][4][4];
    bool qloaded = false;

    const int ITERS = 32;
    for (int it = 0; it < ITERS; ++it) {
        if (it + 1 < ITERS) CP_WAIT(1); else CP_WAIT(0);
        __syncthreads();               // stage it visible; stage (it+2)%3 free
        if (it + 2 < ITERS) issueKV(it + 2, (it + 2) % 3);

        if (!qloaded) {                // Q arrived with group 0
            #pragma unroll
            for (int mt = 0; mt < 2; mt++)
                #pragma unroll
                for (int ks = 0; ks < 4; ks++)
                    ldsm4(qf[mt][ks], sb + A_QS + qoff + mt * 16 * 144 + ks * 32);
            qloaded = true;
        }

        const uint32_t sK = sb + A_KS(it % 3), sV = sb + A_VS(it % 3);

        // ---- S = Q K^T (exp2 domain: q already scaled by 0.125*log2e) ----
        float s[2][8][4];
        #pragma unroll
        for (int mt = 0; mt < 2; mt++)
            #pragma unroll
            for (int i = 0; i < 8; i++)
                #pragma unroll
                for (int j = 0; j < 4; j++) s[mt][i][j] = 0.f;

        #pragma unroll
        for (int ks = 0; ks < 4; ks++) {
            uint32_t kbf[4][4];
            #pragma unroll
            for (int np = 0; np < 4; np++)
                ldsm4(kbf[np], sK + koff + np * 16 * 144 + ks * 32);
            #pragma unroll
            for (int mt = 0; mt < 2; mt++)
                #pragma unroll
                for (int nt = 0; nt < 8; nt++)
                    mma16(s[mt][nt], qf[mt][ks], &kbf[nt >> 1][(nt & 1) * 2]);
        }

        // ---- online softmax (exp2); P packed straight into A-fragments ----
        uint32_t pf[2][4][4];
        #pragma unroll
        for (int mt = 0; mt < 2; mt++) {
            float mx0 = -CUDART_INF_F, mx1 = -CUDART_INF_F;
            #pragma unroll
            for (int nt = 0; nt < 8; nt++) {
                mx0 = fmaxf(mx0, fmaxf(s[mt][nt][0], s[mt][nt][1]));
                mx1 = fmaxf(mx1, fmaxf(s[mt][nt][2], s[mt][nt][3]));
            }
            mx0 = fmaxf(mx0, __shfl_xor_sync(0xffffffffu, mx0, 1));
            mx0 = fmaxf(mx0, __shfl_xor_sync(0xffffffffu, mx0, 2));
            mx1 = fmaxf(mx1, __shfl_xor_sync(0xffffffffu, mx1, 1));
            mx1 = fmaxf(mx1, __shfl_xor_sync(0xffffffffu, mx1, 2));

            const float mn0 = fmaxf(mr[mt][0], mx0), mn1 = fmaxf(mr[mt][1], mx1);
            const float cr0 = exp2f(mr[mt][0] - mn0), cr1 = exp2f(mr[mt][1] - mn1);
            float ps0 = 0.f, ps1 = 0.f;
            #pragma unroll
            for (int nt = 0; nt < 8; nt++) {
                float p00 = exp2f(s[mt][nt][0] - mn0);
                float p01 = exp2f(s[mt][nt][1] - mn0);
                float p10 = exp2f(s[mt][nt][2] - mn1);
                float p11 = exp2f(s[mt][nt][3] - mn1);
                ps0 += p00 + p01;
                ps1 += p10 + p11;
                uint32_t lo = h2u(__floats2half2_rn(p00, p01));
                uint32_t hi = h2u(__floats2half2_rn(p10, p11));
                int kb = nt >> 1;
                if ((nt & 1) == 0) { pf[mt][kb][0] = lo; pf[mt][kb][1] = hi; }
                else               { pf[mt][kb][2] = lo; pf[mt][kb][3] = hi; }
            }
            ps0 += __shfl_xor_sync(0xffffffffu, ps0, 1);
            ps0 += __shfl_xor_sync(0xffffffffu, ps0, 2);
            ps1 += __shfl_xor_sync(0xffffffffu, ps1, 1);
            ps1 += __shfl_xor_sync(0xffffffffu, ps1, 2);
            lr[mt][0] = lr[mt][0] * cr0 + ps0;
            lr[mt][1] = lr[mt][1] * cr1 + ps1;
            mr[mt][0] = mn0; mr[mt][1] = mn1;
            #pragma unroll
            for (int nt = 0; nt < 8; nt++) {
                o[mt][nt][0] *= cr0; o[mt][nt][1] *= cr0;
                o[mt][nt][2] *= cr1; o[mt][nt][3] *= cr1;
            }
        }

        // ---- O += P V ----
        #pragma unroll
        for (int ks = 0; ks < 4; ks++) {
            uint32_t vbf[4][4];
            #pragma unroll
            for (int np = 0; np < 4; np++)
                ldsm4t(vbf[np], sV + voff + ks * 16 * 144 + np * 32);
            #pragma unroll
            for (int mt = 0; mt < 2; mt++)
                #pragma unroll
                for (int nt = 0; nt < 8; nt++)
                    mma16(o[mt][nt], pf[mt][ks], &vbf[nt >> 1][(nt & 1) * 2]);
        }
    }

    // ---- epilogue -> half O ----
    #pragma unroll
    for (int mt = 0; mt < 2; mt++) {
        const float inv0 = 1.f / lr[mt][0], inv1 = 1.f / lr[mt][1];
        const int r0 = q0 + w * 32 + mt * 16 + g;
        #pragma unroll
        for (int nt = 0; nt < 8; nt++) {
            const int col = nt * 8 + 2 * tg;
            __half2 h0 = __floats2half2_rn(o[mt][nt][0] * inv0, o[mt][nt][1] * inv0);
            __half2 h1 = __floats2half2_rn(o[mt][nt][2] * inv1, o[mt][nt][3] * inv1);
            *(__half2*)(Og + ((size_t)bh * Nn + r0) * 64 + col) = h0;
            *(__half2*)(Og + ((size_t)bh * Nn + r0 + 8) * 64 + col) = h1;
        }
    }
}

// ---------------------------------------------------------------------------
extern "C" void kernel_launch(void* const* d_in, const int* in_sizes, int n_in,
                              void* d_out, int out_size)
{
    const float* x       = (const float*)d_in[0];
    const float* w_qkv   = (const float*)d_in[1];
    const float* q_gamma = (const float*)d_in[2];
    const float* q_beta  = (const float*)d_in[3];
    const float* k_gamma = (const float*)d_in[4];
    const float* k_beta  = (const float*)d_in[5];
    const float* w_proj  = (const float*)d_in[6];
    const float* b_proj  = (const float*)d_in[7];
    float* out = (float*)d_out;

    __half *q, *k, *v, *o, *xh, *wq, *wp;
    cudaGetSymbolAddress((void**)&q,  g_q);
    cudaGetSymbolAddress((void**)&k,  g_k);
    cudaGetSymbolAddress((void**)&v,  g_v);
    cudaGetSymbolAddress((void**)&o,  g_o);
    cudaGetSymbolAddress((void**)&xh, g_x);
    cudaGetSymbolAddress((void**)&wq, g_wq);
    cudaGetSymbolAddress((void**)&wp, g_wp);

    cudaFuncSetAttribute(gemm_qkv_ln,
                         cudaFuncAttributeMaxDynamicSharedMemorySize, G_SMEM_B);
    cudaFuncSetAttribute(gemm_proj,
                         cudaFuncAttributeMaxDynamicSharedMemorySize, G_SMEM_B);
    cudaFuncSetAttribute(attn_fp16,
                         cudaFuncAttributeMaxDynamicSharedMemorySize, ATTN_SMEM_B);

    // 0) fp16 conversion of GEMM inputs
    {
        int n4x = Mm * Cc / 4;
        int n4q = Cc * QKVC / 4;
        int n4p = Cc * Cc / 4;
        tohalf4_k<<<(n4x + 255) / 256, 256>>>((const float4*)x, (uint2*)xh, n4x);
        tohalf4_k<<<(n4q + 255) / 256, 256>>>((const float4*)w_qkv, (uint2*)wq, n4q);
        tohalf4_k<<<(n4p + 255) / 256, 256>>>((const float4*)w_proj, (uint2*)wp, n4p);
    }

    // 1) fused qkv GEMM + LayerNorm + split (fp16 in, fp32 LN, fp16 out)
    gemm_qkv_ln<<<dim3(QKVC / 128, Mm / 128), 128, G_SMEM_B>>>(
        xh, wq, q_gamma, q_beta, k_gamma, k_beta, q, k, v);

    // 2) flash attention (fp16 operands, fp32 accum, P in regs, exp2 domain)
    attn_fp16<<<dim3(Nn / 128, BH), 128, ATTN_SMEM_B>>>(q, k, v, o);

    // 3) out = attn_out @ w_proj + b (fp32 out)
    gemm_proj<<<dim3(Cc / 128, Mm / 128), 128, G_SMEM_B>>>(
        o, wp, b_proj, out);
}

// round 12
// speedup vs baseline: 7.9808x; 1.0306x over previous
#include <cuda_runtime.h>
#include <cuda_fp16.h>
#include <math_constants.h>
#include <cstdint>

// Problem constants
#define Bb 4
#define Nn 2048
#define Cc 768
#define Hh 12
#define Dd 64
#define Mm (Bb * Nn)        // 8192
#define QKVC (3 * Cc)       // 2304
#define BH (Bb * Hh)        // 48

// ---------------- scratch (device globals; no allocation allowed) ----------
__device__ __align__(256) __half g_q[(size_t)BH * Nn * Dd];  // [BH,N,D]
__device__ __align__(256) __half g_k[(size_t)BH * Nn * Dd];
__device__ __align__(256) __half g_v[(size_t)BH * Nn * Dd];
__device__ __align__(256) __half g_o[(size_t)BH * Nn * Dd];
__device__ __align__(256) __half g_x[(size_t)Mm * Cc];       // half x
__device__ __align__(256) __half g_wq[(size_t)Cc * QKVC];    // half w_qkv
__device__ __align__(256) __half g_wp[(size_t)Cc * Cc];      // half w_proj

// ===========================================================================
// helpers
// ===========================================================================
__device__ __forceinline__ void mma16(float* d, const uint32_t* a, const uint32_t* b) {
    asm volatile(
        "mma.sync.aligned.m16n8k16.row.col.f32.f16.f16.f32 "
        "{%0,%1,%2,%3}, {%4,%5,%6,%7}, {%8,%9}, {%0,%1,%2,%3};\n"
        : "+f"(d[0]), "+f"(d[1]), "+f"(d[2]), "+f"(d[3])
        : "r"(a[0]), "r"(a[1]), "r"(a[2]), "r"(a[3]),
          "r"(b[0]), "r"(b[1]));
}
__device__ __forceinline__ void ldsm4(uint32_t* r, uint32_t addr) {
    asm volatile("ldmatrix.sync.aligned.m8n8.x4.shared.b16 {%0,%1,%2,%3}, [%4];"
                 : "=r"(r[0]), "=r"(r[1]), "=r"(r[2]), "=r"(r[3]) : "r"(addr));
}
__device__ __forceinline__ void ldsm4t(uint32_t* r, uint32_t addr) {
    asm volatile("ldmatrix.sync.aligned.m8n8.x4.trans.shared.b16 {%0,%1,%2,%3}, [%4];"
                 : "=r"(r[0]), "=r"(r[1]), "=r"(r[2]), "=r"(r[3]) : "r"(addr));
}
__device__ __forceinline__ uint32_t h2u(__half2 h) { return *(uint32_t*)&h; }
__device__ __forceinline__ uint32_t smem_u32(const void* p) {
    uint32_t a;
    asm("{ .reg .u64 t; cvta.to.shared.u64 t, %1; cvt.u32.u64 %0, t; }"
        : "=r"(a) : "l"(p));
    return a;
}
__device__ __forceinline__ void cp16(uint32_t dst, const void* src) {
    asm volatile("cp.async.cg.shared.global [%0], [%1], 16;\n"
                 :: "r"(dst), "l"(src));
}
#define CP_COMMIT() asm volatile("cp.async.commit_group;\n" ::: "memory")
#define CP_WAIT(N)  asm volatile("cp.async.wait_group %0;\n" :: "n"(N) : "memory")

// ===========================================================================
// fused fp32 -> fp16 conversion for all three GEMM inputs (one launch)
// ===========================================================================
#define N4X (Mm * Cc / 4)          // 1572864
#define N4Q (Cc * QKVC / 4)        // 442368
#define N4P (Cc * Cc / 4)          // 147456
#define N4ALL (N4X + N4Q + N4P)    // 2162688

__global__ void tohalf_all_k(const float4* __restrict__ x,
                             const float4* __restrict__ wq,
                             const float4* __restrict__ wp,
                             uint2* __restrict__ xo,
                             uint2* __restrict__ wqo,
                             uint2* __restrict__ wpo)
{
    int i = blockIdx.x * blockDim.x + threadIdx.x;
    if (i >= N4ALL) return;
    const float4* src;
    uint2* dst;
    int j;
    if (i < N4X)            { src = x;  dst = xo;  j = i; }
    else if (i < N4X + N4Q) { src = wq; dst = wqo; j = i - N4X; }
    else                    { src = wp; dst = wpo; j = i - N4X - N4Q; }
    float4 v = src[j];
    __half2 h0 = __floats2half2_rn(v.x, v.y);
    __half2 h1 = __floats2half2_rn(v.z, v.w);
    dst[j] = make_uint2(h2u(h0), h2u(h1));
}

// ===========================================================================
// fp16 GEMM smem (3 stages, k-chunk 32): As[128][40h]=10240 B, Bs[32][136h]=8704 B.
// ===========================================================================
#define GA(s) ((s) * 10240)
#define GB(s) (30720 + (s) * 8704)
#define G_SMEM_B 67584      // max(3-stage pipeline 56832, Cs 128*132*4)

// ---------------------------------------------------------------------------
// fused qkv GEMM + LayerNorm + split. 128 thr (4 warps), warp 64x64,
// CTA tile 128x128 (2 heads), k-chunk 32 (2 k16 steps). Outputs half q/k/v.
// q output folds 0.125 * log2(e) (attention works in exp2 domain).
// ---------------------------------------------------------------------------
__global__ __launch_bounds__(128, 2) void gemm_qkv_ln(
    const __half* __restrict__ A, const __half* __restrict__ Bm,
    const float* __restrict__ qg, const float* __restrict__ qb,
    const float* __restrict__ kg, const float* __restrict__ kb,
    __half* __restrict__ Qo, __half* __restrict__ Ko, __half* __restrict__ Vo)
{
    extern __shared__ float sg[];
    const uint32_t sb = smem_u32(sg);

    const int tid  = threadIdx.x;
    const int lane = tid & 31, wid = tid >> 5;
    const int g = lane >> 2, tg = lane & 3;
    const int wm = (wid & 1) * 64, wn = (wid >> 1) * 64;
    const int m0 = blockIdx.y * 128, n0 = blockIdx.x * 128;
    const int K = Cc, Nc = QKVC;

    float acc[4][8][4];
    #pragma unroll
    for (int i = 0; i < 4; i++)
        #pragma unroll
        for (int j = 0; j < 8; j++)
            #pragma unroll
            for (int r = 0; r < 4; r++) acc[i][j][r] = 0.f;

    auto issue = [&](int it, int s) {
        const int k0 = it * 32;
        #pragma unroll
        for (int i = 0; i < 4; i++) {              // A: 128 rows x 4 chunks
            int idx = tid + i * 128;
            int row = idx >> 2, kk = (idx & 3) * 8;
            cp16(sb + GA(s) + row * 80 + kk * 2,
                 A + (size_t)(m0 + row) * K + k0 + kk);
        }
        #pragma unroll
        for (int i = 0; i < 4; i++) {              // B: 32 rows x 16 chunks
            int idx = tid + i * 128;
            int kr = idx >> 4, nc = (idx & 15) * 8;
            cp16(sb + GB(s) + kr * 272 + nc * 2,
                 Bm + (size_t)(k0 + kr) * Nc + n0 + nc);
        }
        CP_COMMIT();
    };

    // ldmatrix lane bases
    const int j8 = lane >> 3, i8 = lane & 7;
    const uint32_t aoff = (uint32_t)((wm + (j8 & 1) * 8 + i8) * 80 + (j8 >> 1) * 16);
    const int psel = lane >> 4, kh = (lane >> 3) & 1;
    const uint32_t boff = (uint32_t)((kh * 8 + i8) * 272 + (wn + psel * 8) * 2);

    const int ITERS = K / 32;          // 24
    issue(0, 0); issue(1, 1); issue(2, 2);
    CP_WAIT(2);
    __syncthreads();

    for (int it = 0; it < ITERS; ++it) {
        const uint32_t sA = sb + GA(it % 3), sB = sb + GB(it % 3);
        #pragma unroll
        for (int ks = 0; ks < 2; ks++) {
            uint32_t afr[4][4], bfr[4][4];
            #pragma unroll
            for (int mt = 0; mt < 4; mt++)
                ldsm4(afr[mt], sA + aoff + mt * 16 * 80 + ks * 32);
            #pragma unroll
            for (int np = 0; np < 4; np++)
                ldsm4t(bfr[np], sB + boff + ks * 16 * 272 + np * 32);
            #pragma unroll
            for (int mt = 0; mt < 4; mt++)
                #pragma unroll
                for (int nt = 0; nt < 8; nt++)
                    mma16(acc[mt][nt], afr[mt], &bfr[nt >> 1][(nt & 1) * 2]);
        }
        __syncthreads();
        if (it + 3 < ITERS)      { issue(it + 3, (it + 3) % 3); CP_WAIT(2); }
        else if (it + 2 < ITERS) { CP_WAIT(1); }
        else if (it + 1 < ITERS) { CP_WAIT(0); }
        __syncthreads();
    }

    // ---- stage accumulators into Cs[128][132] fp32 ----
    float* Cs = sg;
    #pragma unroll
    for (int mt = 0; mt < 4; mt++) {
        int row = wm + mt * 16 + g;
        #pragma unroll
        for (int nt = 0; nt < 8; nt++) {
            int col = wn + nt * 8 + 2 * tg;
            *(float2*)(Cs + row * 132 + col) =
                make_float2(acc[mt][nt][0], acc[mt][nt][1]);
            *(float2*)(Cs + (row + 8) * 132 + col) =
                make_float2(acc[mt][nt][2], acc[mt][nt][3]);
        }
    }
    __syncthreads();

    // ---- LN / split (outputs half) ----
    const int sect  = n0 / 768;          // 0=q, 1=k, 2=v
    const int hbase = (n0 % 768) / 64;
    const int oct = lane >> 3, li = lane & 7;
    __half* outp = (sect == 0) ? Qo : (sect == 1) ? Ko : Vo;
    const float* gam = (sect == 0) ? qg : kg;
    const float* bet = (sect == 0) ? qb : kb;
    const float qs = (sect == 0) ? 0.125f * 1.44269504f : 1.0f;  // fold log2e

    float4 ga0, ga1, be0, be1;
    if (sect < 2) {
        ga0 = *(const float4*)(gam + li * 8);
        ga1 = *(const float4*)(gam + li * 8 + 4);
        be0 = *(const float4*)(bet + li * 8);
        be1 = *(const float4*)(bet + li * 8 + 4);
    }

    for (int itr = 0; itr < 16; itr++) {
        int rh = wid * 64 + itr * 4 + oct;
        int row = rh >> 1, hh = rh & 1;
        const float* src = Cs + row * 132 + hh * 64 + li * 8;
        float4 f0 = *(const float4*)(src);
        float4 f1 = *(const float4*)(src + 4);
        int token = m0 + row;
        int b = token >> 11, n = token & 2047;
        __half* dst = outp +
            (((size_t)(b * Hh + hbase + hh) * Nn + n) << 6) + li * 8;
        if (sect < 2) {
            float s8 = f0.x + f0.y + f0.z + f0.w + f1.x + f1.y + f1.z + f1.w;
            float q8 = f0.x*f0.x + f0.y*f0.y + f0.z*f0.z + f0.w*f0.w +
                       f1.x*f1.x + f1.y*f1.y + f1.z*f1.z + f1.w*f1.w;
            #pragma unroll
            for (int off = 1; off <= 4; off <<= 1) {
                s8 += __shfl_xor_sync(0xffffffffu, s8, off);
                q8 += __shfl_xor_sync(0xffffffffu, q8, off);
            }
            float mean = s8 * (1.f / 64.f);
            float var  = q8 * (1.f / 64.f) - mean * mean;
            float rstd = rsqrtf(var + 1e-5f);
            f0.x = ((f0.x - mean) * rstd * ga0.x + be0.x) * qs;
            f0.y = ((f0.y - mean) * rstd * ga0.y + be0.y) * qs;
            f0.z = ((f0.z - mean) * rstd * ga0.z + be0.z) * qs;
            f0.w = ((f0.w - mean) * rstd * ga0.w + be0.w) * qs;
            f1.x = ((f1.x - mean) * rstd * ga1.x + be1.x) * qs;
            f1.y = ((f1.y - mean) * rstd * ga1.y + be1.y) * qs;
            f1.z = ((f1.z - mean) * rstd * ga1.z + be1.z) * qs;
            f1.w = ((f1.w - mean) * rstd * ga1.w + be1.w) * qs;
        }
        uint4 u;
        u.x = h2u(__floats2half2_rn(f0.x, f0.y));
        u.y = h2u(__floats2half2_rn(f0.z, f0.w));
        u.z = h2u(__floats2half2_rn(f1.x, f1.y));
        u.w = h2u(__floats2half2_rn(f1.z, f1.w));
        *(uint4*)dst = u;
    }
}

// ===========================================================================
// proj GEMM fp16: out = A@B + bias (fp32 out). A remapped from half [BH,N,D].
// k-chunk 32, 3-stage, two-barrier (round-10 proven schedule).
// ===========================================================================
__global__ __launch_bounds__(128, 2) void gemm_proj(
    const __half* __restrict__ A, const __half* __restrict__ Bm,
    const float* __restrict__ bias, float* __restrict__ C)
{
    extern __shared__ float sg[];
    const uint32_t sb = smem_u32(sg);

    const int tid  = threadIdx.x;
    const int lane = tid & 31, wid = tid >> 5;
    const int g = lane >> 2, tg = lane & 3;
    const int wm = (wid & 1) * 64, wn = (wid >> 1) * 64;
    const int m0 = blockIdx.y * 128, n0 = blockIdx.x * 128;
    const int K = Cc, Nc = Cc;

    float acc[4][8][4];
    #pragma unroll
    for (int i = 0; i < 4; i++)
        #pragma unroll
        for (int j = 0; j < 8; j++)
            #pragma unroll
            for (int r = 0; r < 4; r++) acc[i][j][r] = 0.f;

    auto issue = [&](int it, int s) {
        const int k0 = it * 32;
        #pragma unroll
        for (int i = 0; i < 4; i++) {
            int idx = tid + i * 128;
            int row = idx >> 2, kk = (idx & 3) * 8;
            int gk = k0 + kk;
            int h = gk >> 6, d0 = gk & 63;
            int gm = m0 + row, b = gm >> 11, n = gm & 2047;
            cp16(sb + GA(s) + row * 80 + kk * 2,
                 A + (((size_t)(b * Hh + h) * Nn + n) << 6) + d0);
        }
        #pragma unroll
        for (int i = 0; i < 4; i++) {
            int idx = tid + i * 128;
            int kr = idx >> 4, nc = (idx & 15) * 8;
            cp16(sb + GB(s) + kr * 272 + nc * 2,
                 Bm + (size_t)(k0 + kr) * Nc + n0 + nc);
        }
        CP_COMMIT();
    };

    const int j8 = lane >> 3, i8 = lane & 7;
    const uint32_t aoff = (uint32_t)((wm + (j8 & 1) * 8 + i8) * 80 + (j8 >> 1) * 16);
    const int psel = lane >> 4, kh = (lane >> 3) & 1;
    const uint32_t boff = (uint32_t)((kh * 8 + i8) * 272 + (wn + psel * 8) * 2);

    const int ITERS = K / 32;
    issue(0, 0); issue(1, 1); issue(2, 2);
    CP_WAIT(2);
    __syncthreads();

    for (int it = 0; it < ITERS; ++it) {
        const uint32_t sA = sb + GA(it % 3), sB = sb + GB(it % 3);
        #pragma unroll
        for (int ks = 0; ks < 2; ks++) {
            uint32_t afr[4][4], bfr[4][4];
            #pragma unroll
            for (int mt = 0; mt < 4; mt++)
                ldsm4(afr[mt], sA + aoff + mt * 16 * 80 + ks * 32);
            #pragma unroll
            for (int np = 0; np < 4; np++)
                ldsm4t(bfr[np], sB + boff + ks * 16 * 272 + np * 32);
            #pragma unroll
            for (int mt = 0; mt < 4; mt++)
                #pragma unroll
                for (int nt = 0; nt < 8; nt++)
                    mma16(acc[mt][nt], afr[mt], &bfr[nt >> 1][(nt & 1) * 2]);
        }
        __syncthreads();
        if (it + 3 < ITERS)      { issue(it + 3, (it + 3) % 3); CP_WAIT(2); }
        else if (it + 2 < ITERS) { CP_WAIT(1); }
        else if (it + 1 < ITERS) { CP_WAIT(0); }
        __syncthreads();
    }

    #pragma unroll
    for (int mt = 0; mt < 4; mt++) {
        const int r0 = m0 + wm + mt * 16 + g;
        #pragma unroll
        for (int nt = 0; nt < 8; nt++) {
            const int col = n0 + wn + nt * 8 + 2 * tg;
            float bx = bias[col], by = bias[col + 1];
            float2 v0 = { acc[mt][nt][0] + bx, acc[mt][nt][1] + by };
            float2 v1 = { acc[mt][nt][2] + bx, acc[mt][nt][3] + by };
            *(float2*)(C + (size_t)r0 * Nc + col) = v0;
            *(float2*)(C + (size_t)(r0 + 8) * Nc + col) = v1;
        }
    }
}

// ===========================================================================
// Flash attention fp16. Q-tile 128, 128 thr (4 warps x 32 rows), kv-tile 64,
// 3-stage cp.async, single barrier per iter, exp2 domain, P in registers.
// Smem: Qs[128][72h]=18432, Ks{3}=27648, Vs{3}=27648 -> 73728 B (2 CTAs/SM).
// ===========================================================================
#define A_QS 0
#define A_KS(s) (18432 + (s) * 9216)
#define A_VS(s) (46080 + (s) * 9216)
#define ATTN_SMEM_B 73728

__global__ __launch_bounds__(128, 2) void attn_fp16(
    const __half* __restrict__ Qg, const __half* __restrict__ Kg,
    const __half* __restrict__ Vg, __half* __restrict__ Og)
{
    extern __shared__ float sg[];
    const uint32_t sb = smem_u32(sg);

    const int tid = threadIdx.x, lane = tid & 31, w = tid >> 5;
    const int g = lane >> 2, tg = lane & 3;
    const int bh = blockIdx.y, q0 = blockIdx.x * 128;

    const __half* Qp = Qg + ((size_t)bh * Nn + q0) * 64;
    const __half* Kp = Kg + (size_t)bh * Nn * 64;
    const __half* Vp = Vg + (size_t)bh * Nn * 64;

    auto issueKV = [&](int it, int s) {
        const int k0 = it * 64;
        #pragma unroll
        for (int i = 0; i < 4; i++) {
            int idx = tid + i * 128;
            int row = idx >> 3, c = (idx & 7) * 8;
            cp16(sb + A_KS(s) + row * 144 + c * 2,
                 Kp + (size_t)(k0 + row) * 64 + c);
            cp16(sb + A_VS(s) + row * 144 + c * 2,
                 Vp + (size_t)(k0 + row) * 64 + c);
        }
        CP_COMMIT();
    };

    // prologue: Q + KV0 (group0), KV1 (group1)
    #pragma unroll
    for (int i = 0; i < 8; i++) {
        int idx = tid + i * 128;
        int row = idx >> 3, c = (idx & 7) * 8;
        cp16(sb + A_QS + row * 144 + c * 2, Qp + (size_t)row * 64 + c);
    }
    issueKV(0, 0);
    issueKV(1, 1);

    // ldmatrix lane bases
    const int j8 = lane >> 3, i8 = lane & 7;
    const uint32_t qoff = (uint32_t)((w * 32 + (j8 & 1) * 8 + i8) * 144 + (j8 >> 1) * 16);
    const int ntsel = lane >> 4, dh = (lane >> 3) & 1;        // K (non-trans)
    const uint32_t koff = (uint32_t)((ntsel * 8 + i8) * 144 + dh * 16);
    const int dsel = lane >> 4, kvh = (lane >> 3) & 1;        // V (trans)
    const uint32_t voff = (uint32_t)((kvh * 8 + i8) * 144 + dsel * 16);

    float mr[2][2], lr[2][2];
    #pragma unroll
    for (int mt = 0; mt < 2; mt++) {
        mr[mt][0] = -CUDART_INF_F; mr[mt][1] = -CUDART_INF_F;
        lr[mt][0] = 0.f; lr[mt][1] = 0.f;
    }
    float o[2][8][4];
    #pragma unroll
    for (int mt = 0; mt < 2; mt++)
        #pragma unroll
        for (int i = 0; i < 8; i++)
            #pragma unroll
            for (int j = 0; j < 4; j++) o[mt][i][j] = 0.f;

    uint32_t qf[2][4][4];
    bool qloaded = false;

    const int ITERS = 32;
    for (int it = 0; it < ITERS; ++it) {
        if (it + 1 < ITERS) CP_WAIT(1); else CP_WAIT(0);
        __syncthreads();               // stage it visible; stage (it+2)%3 free
        if (it + 2 < ITERS) issueKV(it + 2, (it + 2) % 3);

        if (!qloaded) {                // Q arrived with group 0
            #pragma unroll
            for (int mt = 0; mt < 2; mt++)
                #pragma unroll
                for (int ks = 0; ks < 4; ks++)
                    ldsm4(qf[mt][ks], sb + A_QS + qoff + mt * 16 * 144 + ks * 32);
            qloaded = true;
        }

        const uint32_t sK = sb + A_KS(it % 3), sV = sb + A_VS(it % 3);

        // ---- S = Q K^T (exp2 domain: q already scaled by 0.125*log2e) ----
        float s[2][8][4];
        #pragma unroll
        for (int mt = 0; mt < 2; mt++)
            #pragma unroll
            for (int i = 0; i < 8; i++)
                #pragma unroll
                for (int j = 0; j < 4; j++) s[mt][i][j] = 0.f;

        #pragma unroll
        for (int ks = 0; ks < 4; ks++) {
            uint32_t kbf[4][4];
            #pragma unroll
            for (int np = 0; np < 4; np++)
                ldsm4(kbf[np], sK + koff + np * 16 * 144 + ks * 32);
            #pragma unroll
            for (int mt = 0; mt < 2; mt++)
                #pragma unroll
                for (int nt = 0; nt < 8; nt++)
                    mma16(s[mt][nt], qf[mt][ks], &kbf[nt >> 1][(nt & 1) * 2]);
        }

        // ---- online softmax (exp2); P packed straight into A-fragments ----
        uint32_t pf[2][4][4];
        #pragma unroll
        for (int mt = 0; mt < 2; mt++) {
            float mx0 = -CUDART_INF_F, mx1 = -CUDART_INF_F;
            #pragma unroll
            for (int nt = 0; nt < 8; nt++) {
                mx0 = fmaxf(mx0, fmaxf(s[mt][nt][0], s[mt][nt][1]));
                mx1 = fmaxf(mx1, fmaxf(s[mt][nt][2], s[mt][nt][3]));
            }
            mx0 = fmaxf(mx0, __shfl_xor_sync(0xffffffffu, mx0, 1));
            mx0 = fmaxf(mx0, __shfl_xor_sync(0xffffffffu, mx0, 2));
            mx1 = fmaxf(mx1, __shfl_xor_sync(0xffffffffu, mx1, 1));
            mx1 = fmaxf(mx1, __shfl_xor_sync(0xffffffffu, mx1, 2));

            const float mn0 = fmaxf(mr[mt][0], mx0), mn1 = fmaxf(mr[mt][1], mx1);
            const float cr0 = exp2f(mr[mt][0] - mn0), cr1 = exp2f(mr[mt][1] - mn1);
            float ps0 = 0.f, ps1 = 0.f;
            #pragma unroll
            for (int nt = 0; nt < 8; nt++) {
                float p00 = exp2f(s[mt][nt][0] - mn0);
                float p01 = exp2f(s[mt][nt][1] - mn0);
                float p10 = exp2f(s[mt][nt][2] - mn1);
                float p11 = exp2f(s[mt][nt][3] - mn1);
                ps0 += p00 + p01;
                ps1 += p10 + p11;
                uint32_t lo = h2u(__floats2half2_rn(p00, p01));
                uint32_t hi = h2u(__floats2half2_rn(p10, p11));
                int kb = nt >> 1;
                if ((nt & 1) == 0) { pf[mt][kb][0] = lo; pf[mt][kb][1] = hi; }
                else               { pf[mt][kb][2] = lo; pf[mt][kb][3] = hi; }
            }
            ps0 += __shfl_xor_sync(0xffffffffu, ps0, 1);
            ps0 += __shfl_xor_sync(0xffffffffu, ps0, 2);
            ps1 += __shfl_xor_sync(0xffffffffu, ps1, 1);
            ps1 += __shfl_xor_sync(0xffffffffu, ps1, 2);
            lr[mt][0] = lr[mt][0] * cr0 + ps0;
            lr[mt][1] = lr[mt][1] * cr1 + ps1;
            mr[mt][0] = mn0; mr[mt][1] = mn1;
            #pragma unroll
            for (int nt = 0; nt < 8; nt++) {
                o[mt][nt][0] *= cr0; o[mt][nt][1] *= cr0;
                o[mt][nt][2] *= cr1; o[mt][nt][3] *= cr1;
            }
        }

        // ---- O += P V ----
        #pragma unroll
        for (int ks = 0; ks < 4; ks++) {
            uint32_t vbf[4][4];
            #pragma unroll
            for (int np = 0; np < 4; np++)
                ldsm4t(vbf[np], sV + voff + ks * 16 * 144 + np * 32);
            #pragma unroll
            for (int mt = 0; mt < 2; mt++)
                #pragma unroll
                for (int nt = 0; nt < 8; nt++)
                    mma16(o[mt][nt], pf[mt][ks], &vbf[nt >> 1][(nt & 1) * 2]);
        }
    }

    // ---- epilogue -> half O ----
    #pragma unroll
    for (int mt = 0; mt < 2; mt++) {
        const float inv0 = 1.f / lr[mt][0], inv1 = 1.f / lr[mt][1];
        const int r0 = q0 + w * 32 + mt * 16 + g;
        #pragma unroll
        for (int nt = 0; nt < 8; nt++) {
            const int col = nt * 8 + 2 * tg;
            __half2 h0 = __floats2half2_rn(o[mt][nt][0] * inv0, o[mt][nt][1] * inv0);
            __half2 h1 = __floats2half2_rn(o[mt][nt][2] * inv1, o[mt][nt][3] * inv1);
            *(__half2*)(Og + ((size_t)bh * Nn + r0) * 64 + col) = h0;
            *(__half2*)(Og + ((size_t)bh * Nn + r0 + 8) * 64 + col) = h1;
        }
    }
}

// ---------------------------------------------------------------------------
extern "C" void kernel_launch(void* const* d_in, const int* in_sizes, int n_in,
                              void* d_out, int out_size)
{
    const float* x       = (const float*)d_in[0];
    const float* w_qkv   = (const float*)d_in[1];
    const float* q_gamma = (const float*)d_in[2];
    const float* q_beta  = (const float*)d_in[3];
    const float* k_gamma = (const float*)d_in[4];
    const float* k_beta  = (const float*)d_in[5];
    const float* w_proj  = (const float*)d_in[6];
    const float* b_proj  = (const float*)d_in[7];
    float* out = (float*)d_out;

    __half *q, *k, *v, *o, *xh, *wq, *wp;
    cudaGetSymbolAddress((void**)&q,  g_q);
    cudaGetSymbolAddress((void**)&k,  g_k);
    cudaGetSymbolAddress((void**)&v,  g_v);
    cudaGetSymbolAddress((void**)&o,  g_o);
    cudaGetSymbolAddress((void**)&xh, g_x);
    cudaGetSymbolAddress((void**)&wq, g_wq);
    cudaGetSymbolAddress((void**)&wp, g_wp);

    cudaFuncSetAttribute(gemm_qkv_ln,
                         cudaFuncAttributeMaxDynamicSharedMemorySize, G_SMEM_B);
    cudaFuncSetAttribute(gemm_proj,
                         cudaFuncAttributeMaxDynamicSharedMemorySize, G_SMEM_B);
    cudaFuncSetAttribute(attn_fp16,
                         cudaFuncAttributeMaxDynamicSharedMemorySize, ATTN_SMEM_B);

    // 0) fused fp16 conversion of all GEMM inputs (one launch)
    tohalf_all_k<<<(N4ALL + 255) / 256, 256>>>(
        (const float4*)x, (const float4*)w_qkv, (const float4*)w_proj,
        (uint2*)xh, (uint2*)wq, (uint2*)wp);

    // 1) fused qkv GEMM + LayerNorm + split (fp16 in, fp32 LN, fp16 out)
    gemm_qkv_ln<<<dim3(QKVC / 128, Mm / 128), 128, G_SMEM_B>>>(
        xh, wq, q_gamma, q_beta, k_gamma, k_beta, q, k, v);

    // 2) flash attention (fp16 operands, fp32 accum, P in regs, exp2 domain)
    attn_fp16<<<dim3(Nn / 128, BH), 128, ATTN_SMEM_B>>>(q, k, v, o);

    // 3) out = attn_out @ w_proj + b (fp32 out)
    gemm_proj<<<dim3(Cc / 128, Mm / 128), 128, G_SMEM_B>>>(
        o, wp, b_proj, out);
}